// round 7
// baseline (speedup 1.0000x reference)
#include <cuda_runtime.h>
#include <cuda_fp16.h>
#include <math.h>

// Problem constants (fixed shapes from reference)
#define BB 16
#define SS 4096
#define DD 64
#define HH 8
#define NBK 64          // buckets per hash round
#define CHK 512         // chunks per batch (HH * NBK)
#define BSZ 64          // bucket/chunk size
#define KVN 128         // keys per chunk (current + look-back)

// -------------------- device scratch (no allocation allowed) --------------------
__device__ int     g_buckets[BB * HH * SS];               // 2 MB
__device__ int     g_st[BB * HH * SS];                    // 2 MB  sorted original positions
__device__ float   g_lse[BB * HH * SS];                   // 2 MB  per-round logits (unsorted layout)
__device__ __half2 g_o[(size_t)BB * HH * SS * 32];        // 67 MB per-round outputs (fp16, unsorted)

// -------------------- helpers --------------------
__device__ __forceinline__ unsigned h2_u32(__half2 h) {
    union { __half2 h; unsigned u; } cvt;
    cvt.h = h;
    return cvt.u;
}

__device__ __forceinline__ void mma_f16(float* c,
                                        unsigned a0, unsigned a1, unsigned a2, unsigned a3,
                                        unsigned b0, unsigned b1) {
    asm volatile("mma.sync.aligned.m16n8k16.row.col.f32.f16.f16.f32 "
                 "{%0,%1,%2,%3},{%4,%5,%6,%7},{%8,%9},{%0,%1,%2,%3};"
                 : "+f"(c[0]), "+f"(c[1]), "+f"(c[2]), "+f"(c[3])
                 : "r"(a0), "r"(a1), "r"(a2), "r"(a3), "r"(b0), "r"(b1));
}

// VT column permutation: places keys j and j+8 in adjacent half slots so a PV
// B-fragment (keys {j, j+8} lo/hi, {j+1, j+9}) is one 8B load.
__device__ __forceinline__ int vperm(int j) {
    return ((j >> 4) << 4) | ((j & 7) << 1) | ((j >> 3) & 1);
}

// ==================== Kernel 1: LSH hashing (fp32 — argmax is discrete) ====================
// grid = BB * (SS/64) = 1024 CTAs, 256 threads.
__global__ __launch_bounds__(256, 2) void hash_kernel(const float* __restrict__ qk,
                                                      const float* __restrict__ rot) {
    extern __shared__ float sm[];
    float* qT  = sm;              // 64*68 floats
    float* big = sm + 64 * 68;    // max(64*260, 256*68) = 17408 floats

    const int blk  = blockIdx.x;
    const int b    = blk >> 6;
    const int t0   = (blk & 63) * 64;
    const int tid  = threadIdx.x;
    const int w    = tid >> 5, l = tid & 31;

    {
        const float4* rg = (const float4*)rot;
        for (int i4 = tid; i4 < 64 * 64; i4 += 256) {
            int f = i4 >> 6, o4 = i4 & 63;
            *(float4*)&big[f * 260 + o4 * 4] = rg[i4];
        }
    }
    for (int r = 0; r < 8; r++) {
        int i = w * 8 + r;
        float2 qv = ((const float2*)(qk + ((size_t)b * SS + t0 + i) * DD))[l];
        qT[(2 * l) * 68 + i]     = qv.x;
        qT[(2 * l + 1) * 68 + i] = qv.y;
    }
    __syncthreads();

    const int rt = tid >> 4, ct = tid & 15;
    float acc[4][16];
#pragma unroll
    for (int r = 0; r < 4; r++)
#pragma unroll
        for (int c = 0; c < 16; c++) acc[r][c] = 0.f;

    const float4* qT4 = (const float4*)qT;   // stride 17
    const float4* rt4 = (const float4*)big;  // stride 65
#pragma unroll 4
    for (int f = 0; f < 64; f++) {
        float4 q = qT4[f * 17 + rt];
        float qa[4] = {q.x, q.y, q.z, q.w};
#pragma unroll
        for (int g = 0; g < 4; g++) {
            float4 rv = rt4[f * 65 + g * 16 + ct];
            float ra[4] = {rv.x, rv.y, rv.z, rv.w};
#pragma unroll
            for (int r = 0; r < 4; r++)
#pragma unroll
                for (int c = 0; c < 4; c++)
                    acc[r][g * 4 + c] += qa[r] * ra[c];
        }
    }
    __syncthreads();

    float* dsH = big;
#pragma unroll
    for (int g = 0; g < 4; g++)
#pragma unroll
        for (int c = 0; c < 4; c++) {
            int o = g * 64 + ct * 4 + c;
            *(float4*)&dsH[o * 68 + rt * 4] =
                make_float4(acc[0][g * 4 + c], acc[1][g * 4 + c], acc[2][g * 4 + c], acc[3][g * 4 + c]);
        }
    __syncthreads();

    for (int p = tid; p < 512; p += 256) {
        int t = p & 63, hh = p >> 6;
        const float* dv = &dsH[(hh * 32) * 68 + t];
        float best = dv[0];
        int bi = 0;
#pragma unroll
        for (int j = 1; j < 32; j++) { float vv = dv[j * 68];  if (vv > best) { best = vv; bi = j; } }
#pragma unroll
        for (int j = 0; j < 32; j++) { float vv = -dv[j * 68]; if (vv > best) { best = vv; bi = 32 + j; } }
        g_buckets[((size_t)(b * HH + hh)) * SS + t0 + t] = bi;
    }
}

// ==================== Kernel 2: stable counting sort per (b,h) ====================
__global__ __launch_bounds__(512) void sort_kernel() {
    __shared__ int hist[16][64];
    __shared__ int run[16][64];
    __shared__ int totals[64];
    __shared__ int bstart[64];

    const int bh  = blockIdx.x;
    const int* bk = g_buckets + (size_t)bh * SS;
    int* dst      = g_st + (size_t)bh * SS;
    const int tid = threadIdx.x, w = tid >> 5, l = tid & 31;

    for (int i = tid; i < 1024; i += 512) ((int*)hist)[i] = 0;
    __syncthreads();

    for (int r = 0; r < 8; r++) {
        int t = w * 256 + r * 32 + l;
        int vv = bk[t];
        unsigned mask = __match_any_sync(0xffffffffu, vv);
        if (l == (int)(__ffs(mask) - 1)) hist[w][vv] += __popc(mask);
        __syncwarp();
    }
    __syncthreads();

    if (tid < 64) {
        int s = 0;
        for (int ww = 0; ww < 16; ww++) { int tmp = hist[ww][tid]; hist[ww][tid] = s; s += tmp; }
        totals[tid] = s;
    }
    __syncthreads();
    if (tid == 0) {
        int s = 0;
        for (int vv = 0; vv < 64; vv++) { bstart[vv] = s; s += totals[vv]; }
    }
    __syncthreads();
    for (int i = tid; i < 1024; i += 512) {
        int ww = i >> 6, vv = i & 63;
        run[ww][vv] = bstart[vv] + hist[ww][vv];
    }
    __syncthreads();

    for (int r = 0; r < 8; r++) {
        int t = w * 256 + r * 32 + l;
        int vv = bk[t];
        unsigned mask = __match_any_sync(0xffffffffu, vv);
        int rank = __popc(mask & ((1u << l) - 1u));
        int base = run[w][vv];
        __syncwarp();
        if (l == (int)(__ffs(mask) - 1)) run[w][vv] = base + __popc(mask);
        __syncwarp();
        dst[base + rank] = t;
    }
}

// ==================== Kernel 3: chunked attention (fp16 mma, register softmax) ====================
// grid = BB*CHK = 8192 CTAs, 256 threads (8 warps), 49920B smem, 2 CTAs/SM (128 regs, no spill).
__global__ __launch_bounds__(256, 2) void attn_kernel(const float* __restrict__ qk,
                                                      const float* __restrict__ v) {
    extern __shared__ char smc[];
    int*    tqi   = (int*)smc;
    int*    tki   = (int*)(smc + 256);
    float*  stats = (float*)(smc + 768);        // [wn*64 + row]*2 -> {m, s}
    __half* Qsm   = (__half*)(smc + 1792);      // stride 80
    __half* Ksm   = (__half*)(smc + 12032);     // stride 80
    __half* VT    = (__half*)(smc + 32512);     // stride 136, VT[f][vperm(j)] = v[j][f]
    float*  Dx    = (float*)(smc + 1792);       // 64 x 66 (aliases Qsm/Ksm after QK)

    const int blk = blockIdx.x;
    const int b = blk >> 9, c = blk & 511;
    const int h  = c >> 6;
    const int cp = (c + 511) & 511;
    const int hp = cp >> 6;
    const int tid = threadIdx.x, w = tid >> 5, l = tid & 31;
    const int gID = l >> 2, tig = l & 3;
    const int wm = w & 3, wn = w >> 2;
    const int arow = wm * 16 + gID;

    if (tid < 64) {
        int t = g_st[((size_t)(b * HH + h)) * SS + (c & 63) * 64 + tid];
        tqi[tid] = t;
        tki[tid] = t;
    } else if (tid < 128) {
        int i = tid - 64;
        tki[64 + i] = g_st[((size_t)(b * HH + hp)) * SS + (cp & 63) * 64 + i];
    }
    __syncthreads();

    // ---- gather: q (scaled), k (normalized), v -> fp16 smem
    for (int r = 0; r < 8; r++) {
        int i = w * 8 + r;
        float2 qv = ((const float2*)(qk + ((size_t)b * SS + tqi[i]) * DD))[l];
        *(__half2*)&Qsm[i * 80 + 2 * l] = __floats2half2_rn(qv.x * 0.125f, qv.y * 0.125f);
    }
    for (int r = 0; r < 16; r++) {
        int j = w * 16 + r;
        int t = tki[j];
        float2 kv = ((const float2*)(qk + ((size_t)b * SS + t) * DD))[l];
        float ssq = kv.x * kv.x + kv.y * kv.y;
#pragma unroll
        for (int o = 16; o; o >>= 1) ssq += __shfl_xor_sync(0xffffffffu, ssq, o);
        float inv = 1.0f / fmaxf(sqrtf(ssq), 1e-12f);
        *(__half2*)&Ksm[j * 80 + 2 * l] = __floats2half2_rn(kv.x * inv, kv.y * inv);
        float2 vv = ((const float2*)(v + ((size_t)b * SS + t) * DD))[l];
        int jp = vperm(j);
        VT[(2 * l) * 136 + jp]     = __float2half_rn(vv.x);
        VT[(2 * l + 1) * 136 + jp] = __float2half_rn(vv.y);
    }
    __syncthreads();

    // ---- QK^T via fp16 mma (K=64, 4 k16 steps, 8 n-tiles)
    float cqk[8][4];
#pragma unroll
    for (int nt = 0; nt < 8; nt++)
#pragma unroll
        for (int r = 0; r < 4; r++) cqk[nt][r] = 0.f;

#pragma unroll
    for (int s = 0; s < 4; s++) {
        uint2 A0 = *(uint2*)&Qsm[arow * 80 + s * 16 + 4 * tig];        // a0 (kL), a2 (kH)
        uint2 A1 = *(uint2*)&Qsm[(arow + 8) * 80 + s * 16 + 4 * tig];  // a1, a3
#pragma unroll
        for (int nt = 0; nt < 8; nt++) {
            uint2 Bv = *(uint2*)&Ksm[(wn * 64 + nt * 8 + gID) * 80 + s * 16 + 4 * tig]; // b0, b1
            mma_f16(cqk[nt], A0.x, A1.x, A0.y, A1.y, Bv.x, Bv.y);
        }
    }

    // ---- self-mask (thread cols: wn*64 + nt*8 + 2tig + {0,1})
    const int tq0 = tqi[arow], tq1 = tqi[arow + 8];
#pragma unroll
    for (int nt = 0; nt < 8; nt++) {
        int2 kk = *(int2*)&tki[wn * 64 + nt * 8 + 2 * tig];
        if (kk.x == tq0) cqk[nt][0] = -5e4f;
        if (kk.y == tq0) cqk[nt][1] = -5e4f;
        if (kk.x == tq1) cqk[nt][2] = -5e4f;
        if (kk.y == tq1) cqk[nt][3] = -5e4f;
    }

    // ---- register softmax: per-row partial (m, s) within warp half, merge across wn
    float m0 = -3.4e38f, m1 = -3.4e38f;
#pragma unroll
    for (int nt = 0; nt < 8; nt++) {
        m0 = fmaxf(m0, fmaxf(cqk[nt][0], cqk[nt][1]));
        m1 = fmaxf(m1, fmaxf(cqk[nt][2], cqk[nt][3]));
    }
    m0 = fmaxf(m0, __shfl_xor_sync(0xffffffffu, m0, 1));
    m0 = fmaxf(m0, __shfl_xor_sync(0xffffffffu, m0, 2));
    m1 = fmaxf(m1, __shfl_xor_sync(0xffffffffu, m1, 1));
    m1 = fmaxf(m1, __shfl_xor_sync(0xffffffffu, m1, 2));
    float s0 = 0.f, s1 = 0.f;
#pragma unroll
    for (int nt = 0; nt < 8; nt++) {
        float e0 = __expf(cqk[nt][0] - m0), e1 = __expf(cqk[nt][1] - m0);
        float e2 = __expf(cqk[nt][2] - m1), e3 = __expf(cqk[nt][3] - m1);
        cqk[nt][0] = e0; cqk[nt][1] = e1; cqk[nt][2] = e2; cqk[nt][3] = e3;
        s0 += e0 + e1; s1 += e2 + e3;
    }
    s0 += __shfl_xor_sync(0xffffffffu, s0, 1);
    s0 += __shfl_xor_sync(0xffffffffu, s0, 2);
    s1 += __shfl_xor_sync(0xffffffffu, s1, 1);
    s1 += __shfl_xor_sync(0xffffffffu, s1, 2);
    if (tig == 0) {
        stats[(wn * 64 + arow) * 2]         = m0;
        stats[(wn * 64 + arow) * 2 + 1]     = s0;
        stats[(wn * 64 + arow + 8) * 2]     = m1;
        stats[(wn * 64 + arow + 8) * 2 + 1] = s1;
    }
    __syncthreads();
    float om0 = stats[((wn ^ 1) * 64 + arow) * 2];
    float os0 = stats[((wn ^ 1) * 64 + arow) * 2 + 1];
    float om1 = stats[((wn ^ 1) * 64 + arow + 8) * 2];
    float os1 = stats[((wn ^ 1) * 64 + arow + 8) * 2 + 1];
    float M0 = fmaxf(m0, om0), M1 = fmaxf(m1, om1);
    float S0 = s0 * __expf(m0 - M0) + os0 * __expf(om0 - M0);
    float S1 = s1 * __expf(m1 - M1) + os1 * __expf(om1 - M1);
    float sc0 = __expf(m0 - M0) / S0;
    float sc1 = __expf(m1 - M1) / S1;
    if (wn == 0 && tig == 0) {
        g_lse[((size_t)(b * HH + h)) * SS + tq0] = M0 + __logf(S0);
        g_lse[((size_t)(b * HH + h)) * SS + tq1] = M1 + __logf(S1);
    }

    // ---- P @ V over this warp's 64-key half (K=64, 4 k16 steps), full f range (8 n-tiles)
    // A fragments pair cqk[2s] (keys j0) with cqk[2s+1] (keys j0+8) to match permuted VT.
    float oacc[8][4];
#pragma unroll
    for (int ft = 0; ft < 8; ft++)
#pragma unroll
        for (int r = 0; r < 4; r++) oacc[ft][r] = 0.f;

#pragma unroll
    for (int s = 0; s < 4; s++) {
        unsigned a0 = h2_u32(__floats2half2_rn(cqk[2 * s][0] * sc0, cqk[2 * s + 1][0] * sc0));
        unsigned a2 = h2_u32(__floats2half2_rn(cqk[2 * s][1] * sc0, cqk[2 * s + 1][1] * sc0));
        unsigned a1 = h2_u32(__floats2half2_rn(cqk[2 * s][2] * sc1, cqk[2 * s + 1][2] * sc1));
        unsigned a3 = h2_u32(__floats2half2_rn(cqk[2 * s][3] * sc1, cqk[2 * s + 1][3] * sc1));
        int pbase = wn * 64 + s * 16 + 4 * tig;
#pragma unroll
        for (int ft = 0; ft < 8; ft++) {
            uint2 Bv = *(uint2*)&VT[(ft * 8 + gID) * 136 + pbase];  // (j0,j0+8), (j0+1,j0+9)
            mma_f16(oacc[ft], a0, a1, a2, a3, Bv.x, Bv.y);
        }
    }

    // ---- sum wn partials via Dx, store fp16 outputs by original token position
    if (wn == 1) {
#pragma unroll
        for (int ft = 0; ft < 8; ft++) {
            *(float2*)&Dx[arow * 66 + ft * 8 + 2 * tig]       = make_float2(oacc[ft][0], oacc[ft][1]);
            *(float2*)&Dx[(arow + 8) * 66 + ft * 8 + 2 * tig] = make_float2(oacc[ft][2], oacc[ft][3]);
        }
    }
    __syncthreads();
    if (wn == 0) {
        __half2* o0 = g_o + (((size_t)(b * HH + h)) * SS + tq0) * 32;
        __half2* o1 = g_o + (((size_t)(b * HH + h)) * SS + tq1) * 32;
#pragma unroll
        for (int ft = 0; ft < 8; ft++) {
            float2 d0 = *(float2*)&Dx[arow * 66 + ft * 8 + 2 * tig];
            float2 d1 = *(float2*)&Dx[(arow + 8) * 66 + ft * 8 + 2 * tig];
            o0[ft * 4 + tig] = __floats2half2_rn(oacc[ft][0] + d0.x, oacc[ft][1] + d0.y);
            o1[ft * 4 + tig] = __floats2half2_rn(oacc[ft][2] + d1.x, oacc[ft][3] + d1.y);
        }
    }
}

// ==================== Kernel 4: combine hash rounds ====================
__global__ __launch_bounds__(256) void combine_kernel(float* __restrict__ out) {
    const int gw = (blockIdx.x * 256 + threadIdx.x) >> 5;
    const int l  = threadIdx.x & 31;
    const int b  = gw >> 12, t = gw & (SS - 1);

    float lg[HH];
#pragma unroll
    for (int hh = 0; hh < HH; hh++) lg[hh] = g_lse[((size_t)(b * HH + hh)) * SS + t];
    float m = lg[0];
#pragma unroll
    for (int hh = 1; hh < HH; hh++) m = fmaxf(m, lg[hh]);
    float wv[HH];
    float wsum = 0.f;
#pragma unroll
    for (int hh = 0; hh < HH; hh++) { wv[hh] = __expf(lg[hh] - m); wsum += wv[hh]; }
    float inv = 1.0f / wsum;

    float2 accv = make_float2(0.f, 0.f);
#pragma unroll
    for (int hh = 0; hh < HH; hh++) {
        float2 ov = __half22float2(g_o[((((size_t)(b * HH + hh)) * SS + t) * 32) + l]);
        float wgt = wv[hh] * inv;
        accv.x += wgt * ov.x;
        accv.y += wgt * ov.y;
    }
    ((float2*)(out + ((size_t)b * SS + t) * DD))[l] = accv;
}

// ==================== launch ====================
extern "C" void kernel_launch(void* const* d_in, const int* in_sizes, int n_in,
                              void* d_out, int out_size) {
    const float* qk  = (const float*)d_in[0];
    const float* v   = (const float*)d_in[1];
    const float* rot = (const float*)d_in[2];
    float* out = (float*)d_out;

    (void)in_sizes; (void)n_in; (void)out_size;

    const int hash_smem = 87040;   // 64*68*4 + 256*68*4
    const int attn_smem = 49920;   // tqi/tki/stats + Qsm + Ksm + VT
    cudaFuncSetAttribute(hash_kernel, cudaFuncAttributeMaxDynamicSharedMemorySize, hash_smem);
    cudaFuncSetAttribute(attn_kernel, cudaFuncAttributeMaxDynamicSharedMemorySize, attn_smem);

    hash_kernel<<<BB * (SS / 64), 256, hash_smem>>>(qk, rot);
    sort_kernel<<<BB * HH, 512>>>();
    attn_kernel<<<BB * CHK, 256, attn_smem>>>(qk, v);
    combine_kernel<<<(BB * SS) / 8, 256>>>(out);
}

// round 8
// speedup vs baseline: 1.2070x; 1.2070x over previous
#include <cuda_runtime.h>
#include <cuda_fp16.h>
#include <math.h>

// Problem constants (fixed shapes from reference)
#define BB 16
#define SS 4096
#define DD 64
#define HH 8
#define NBK 64          // buckets per hash round
#define CHK 512         // chunks per batch (HH * NBK)
#define BSZ 64          // bucket/chunk size
#define KVN 128         // keys per chunk (current + look-back)

// -------------------- device scratch (no allocation allowed) --------------------
__device__ int     g_buckets[BB * HH * SS];               // 2 MB
__device__ int     g_st[BB * HH * SS];                    // 2 MB  sorted original positions
__device__ float   g_lse[BB * HH * SS];                   // 2 MB  per-round logits (unsorted layout)
__device__ __half2 g_o[(size_t)BB * HH * SS * 32];        // 67 MB per-round outputs (fp16, unsorted)

// -------------------- helpers --------------------
__device__ __forceinline__ unsigned h2_u32(__half2 h) {
    union { __half2 h; unsigned u; } cvt;
    cvt.h = h;
    return cvt.u;
}

__device__ __forceinline__ void mma_f16(float* c,
                                        unsigned a0, unsigned a1, unsigned a2, unsigned a3,
                                        unsigned b0, unsigned b1) {
    asm volatile("mma.sync.aligned.m16n8k16.row.col.f32.f16.f16.f32 "
                 "{%0,%1,%2,%3},{%4,%5,%6,%7},{%8,%9},{%0,%1,%2,%3};"
                 : "+f"(c[0]), "+f"(c[1]), "+f"(c[2]), "+f"(c[3])
                 : "r"(a0), "r"(a1), "r"(a2), "r"(a3), "r"(b0), "r"(b1));
}

// VT column permutation: places keys j and j+8 in adjacent half slots so a PV
// B-fragment (keys {j, j+8} lo/hi, {j+1, j+9}) is one 8B load.
__device__ __forceinline__ int vperm(int j) {
    return ((j >> 4) << 4) | ((j & 7) << 1) | ((j >> 3) & 1);
}

// ==================== Kernel 1: LSH hashing (fp32 — argmax is discrete) ====================
// grid = BB * (SS/64) = 1024 CTAs, 256 threads.
__global__ __launch_bounds__(256, 2) void hash_kernel(const float* __restrict__ qk,
                                                      const float* __restrict__ rot) {
    extern __shared__ float sm[];
    float* qT  = sm;              // 64*68 floats
    float* big = sm + 64 * 68;    // max(64*260, 256*68) = 17408 floats

    const int blk  = blockIdx.x;
    const int b    = blk >> 6;
    const int t0   = (blk & 63) * 64;
    const int tid  = threadIdx.x;
    const int w    = tid >> 5, l = tid & 31;

    {
        const float4* rg = (const float4*)rot;
        for (int i4 = tid; i4 < 64 * 64; i4 += 256) {
            int f = i4 >> 6, o4 = i4 & 63;
            *(float4*)&big[f * 260 + o4 * 4] = rg[i4];
        }
    }
    for (int r = 0; r < 8; r++) {
        int i = w * 8 + r;
        float2 qv = ((const float2*)(qk + ((size_t)b * SS + t0 + i) * DD))[l];
        qT[(2 * l) * 68 + i]     = qv.x;
        qT[(2 * l + 1) * 68 + i] = qv.y;
    }
    __syncthreads();

    const int rt = tid >> 4, ct = tid & 15;
    float acc[4][16];
#pragma unroll
    for (int r = 0; r < 4; r++)
#pragma unroll
        for (int c = 0; c < 16; c++) acc[r][c] = 0.f;

    const float4* qT4 = (const float4*)qT;   // stride 17
    const float4* rt4 = (const float4*)big;  // stride 65
#pragma unroll 4
    for (int f = 0; f < 64; f++) {
        float4 q = qT4[f * 17 + rt];
        float qa[4] = {q.x, q.y, q.z, q.w};
#pragma unroll
        for (int g = 0; g < 4; g++) {
            float4 rv = rt4[f * 65 + g * 16 + ct];
            float ra[4] = {rv.x, rv.y, rv.z, rv.w};
#pragma unroll
            for (int r = 0; r < 4; r++)
#pragma unroll
                for (int c = 0; c < 4; c++)
                    acc[r][g * 4 + c] += qa[r] * ra[c];
        }
    }
    __syncthreads();

    float* dsH = big;
#pragma unroll
    for (int g = 0; g < 4; g++)
#pragma unroll
        for (int c = 0; c < 4; c++) {
            int o = g * 64 + ct * 4 + c;
            *(float4*)&dsH[o * 68 + rt * 4] =
                make_float4(acc[0][g * 4 + c], acc[1][g * 4 + c], acc[2][g * 4 + c], acc[3][g * 4 + c]);
        }
    __syncthreads();

    for (int p = tid; p < 512; p += 256) {
        int t = p & 63, hh = p >> 6;
        const float* dv = &dsH[(hh * 32) * 68 + t];
        float best = dv[0];
        int bi = 0;
#pragma unroll
        for (int j = 1; j < 32; j++) { float vv = dv[j * 68];  if (vv > best) { best = vv; bi = j; } }
#pragma unroll
        for (int j = 0; j < 32; j++) { float vv = -dv[j * 68]; if (vv > best) { best = vv; bi = 32 + j; } }
        g_buckets[((size_t)(b * HH + hh)) * SS + t0 + t] = bi;
    }
}

// ==================== Kernel 2: stable counting sort per (b,h) ====================
__global__ __launch_bounds__(512) void sort_kernel() {
    __shared__ int hist[16][64];
    __shared__ int run[16][64];
    __shared__ int totals[64];
    __shared__ int bstart[64];

    const int bh  = blockIdx.x;
    const int* bk = g_buckets + (size_t)bh * SS;
    int* dst      = g_st + (size_t)bh * SS;
    const int tid = threadIdx.x, w = tid >> 5, l = tid & 31;

    for (int i = tid; i < 1024; i += 512) ((int*)hist)[i] = 0;
    __syncthreads();

    for (int r = 0; r < 8; r++) {
        int t = w * 256 + r * 32 + l;
        int vv = bk[t];
        unsigned mask = __match_any_sync(0xffffffffu, vv);
        if (l == (int)(__ffs(mask) - 1)) hist[w][vv] += __popc(mask);
        __syncwarp();
    }
    __syncthreads();

    if (tid < 64) {
        int s = 0;
        for (int ww = 0; ww < 16; ww++) { int tmp = hist[ww][tid]; hist[ww][tid] = s; s += tmp; }
        totals[tid] = s;
    }
    __syncthreads();
    if (tid == 0) {
        int s = 0;
        for (int vv = 0; vv < 64; vv++) { bstart[vv] = s; s += totals[vv]; }
    }
    __syncthreads();
    for (int i = tid; i < 1024; i += 512) {
        int ww = i >> 6, vv = i & 63;
        run[ww][vv] = bstart[vv] + hist[ww][vv];
    }
    __syncthreads();

    for (int r = 0; r < 8; r++) {
        int t = w * 256 + r * 32 + l;
        int vv = bk[t];
        unsigned mask = __match_any_sync(0xffffffffu, vv);
        int rank = __popc(mask & ((1u << l) - 1u));
        int base = run[w][vv];
        __syncwarp();
        if (l == (int)(__ffs(mask) - 1)) run[w][vv] = base + __popc(mask);
        __syncwarp();
        dst[base + rank] = t;
    }
}

// ==================== Kernel 3: chunked attention (fp16 mma, register softmax) ====================
// grid = BB*CHK = 8192 CTAs, 256 threads (8 warps), 49920B smem, 3 CTAs/SM (measured faster than 2).
__global__ __launch_bounds__(256, 3) void attn_kernel(const float* __restrict__ qk,
                                                      const float* __restrict__ v) {
    extern __shared__ char smc[];
    int*    tqi   = (int*)smc;
    int*    tki   = (int*)(smc + 256);
    float*  stats = (float*)(smc + 768);        // [wn*64 + row]*2 -> {m, s}
    __half* Qsm   = (__half*)(smc + 1792);      // stride 80
    __half* Ksm   = (__half*)(smc + 12032);     // stride 80
    __half* VT    = (__half*)(smc + 32512);     // stride 136, VT[f][vperm(j)] = v[j][f]
    float*  Dx    = (float*)(smc + 1792);       // 64 x 66 (aliases Qsm/Ksm after QK)

    const int blk = blockIdx.x;
    const int b = blk >> 9, c = blk & 511;
    const int h  = c >> 6;
    const int cp = (c + 511) & 511;
    const int hp = cp >> 6;
    const int tid = threadIdx.x, w = tid >> 5, l = tid & 31;
    const int gID = l >> 2, tig = l & 3;
    const int wm = w & 3, wn = w >> 2;
    const int arow = wm * 16 + gID;

    if (tid < 64) {
        int t = g_st[((size_t)(b * HH + h)) * SS + (c & 63) * 64 + tid];
        tqi[tid] = t;
        tki[tid] = t;
    } else if (tid < 128) {
        int i = tid - 64;
        tki[64 + i] = g_st[((size_t)(b * HH + hp)) * SS + (cp & 63) * 64 + i];
    }
    __syncthreads();

    // ---- gather: q (scaled), k (normalized), v -> fp16 smem
    for (int r = 0; r < 8; r++) {
        int i = w * 8 + r;
        float2 qv = ((const float2*)(qk + ((size_t)b * SS + tqi[i]) * DD))[l];
        *(__half2*)&Qsm[i * 80 + 2 * l] = __floats2half2_rn(qv.x * 0.125f, qv.y * 0.125f);
    }
    for (int r = 0; r < 16; r++) {
        int j = w * 16 + r;
        int t = tki[j];
        float2 kv = ((const float2*)(qk + ((size_t)b * SS + t) * DD))[l];
        float ssq = kv.x * kv.x + kv.y * kv.y;
#pragma unroll
        for (int o = 16; o; o >>= 1) ssq += __shfl_xor_sync(0xffffffffu, ssq, o);
        float inv = 1.0f / fmaxf(sqrtf(ssq), 1e-12f);
        *(__half2*)&Ksm[j * 80 + 2 * l] = __floats2half2_rn(kv.x * inv, kv.y * inv);
        float2 vv = ((const float2*)(v + ((size_t)b * SS + t) * DD))[l];
        int jp = vperm(j);
        VT[(2 * l) * 136 + jp]     = __float2half_rn(vv.x);
        VT[(2 * l + 1) * 136 + jp] = __float2half_rn(vv.y);
    }
    __syncthreads();

    // ---- QK^T via fp16 mma (K=64, 4 k16 steps, 8 n-tiles)
    float cqk[8][4];
#pragma unroll
    for (int nt = 0; nt < 8; nt++)
#pragma unroll
        for (int r = 0; r < 4; r++) cqk[nt][r] = 0.f;

#pragma unroll
    for (int s = 0; s < 4; s++) {
        uint2 A0 = *(uint2*)&Qsm[arow * 80 + s * 16 + 4 * tig];        // a0 (kL), a2 (kH)
        uint2 A1 = *(uint2*)&Qsm[(arow + 8) * 80 + s * 16 + 4 * tig];  // a1, a3
#pragma unroll
        for (int nt = 0; nt < 8; nt++) {
            uint2 Bv = *(uint2*)&Ksm[(wn * 64 + nt * 8 + gID) * 80 + s * 16 + 4 * tig]; // b0, b1
            mma_f16(cqk[nt], A0.x, A1.x, A0.y, A1.y, Bv.x, Bv.y);
        }
    }

    // ---- self-mask (thread cols: wn*64 + nt*8 + 2tig + {0,1})
    const int tq0 = tqi[arow], tq1 = tqi[arow + 8];
#pragma unroll
    for (int nt = 0; nt < 8; nt++) {
        int2 kk = *(int2*)&tki[wn * 64 + nt * 8 + 2 * tig];
        if (kk.x == tq0) cqk[nt][0] = -5e4f;
        if (kk.y == tq0) cqk[nt][1] = -5e4f;
        if (kk.x == tq1) cqk[nt][2] = -5e4f;
        if (kk.y == tq1) cqk[nt][3] = -5e4f;
    }

    // ---- register softmax: per-row partial (m, s) within warp half, merge across wn
    float m0 = -3.4e38f, m1 = -3.4e38f;
#pragma unroll
    for (int nt = 0; nt < 8; nt++) {
        m0 = fmaxf(m0, fmaxf(cqk[nt][0], cqk[nt][1]));
        m1 = fmaxf(m1, fmaxf(cqk[nt][2], cqk[nt][3]));
    }
    m0 = fmaxf(m0, __shfl_xor_sync(0xffffffffu, m0, 1));
    m0 = fmaxf(m0, __shfl_xor_sync(0xffffffffu, m0, 2));
    m1 = fmaxf(m1, __shfl_xor_sync(0xffffffffu, m1, 1));
    m1 = fmaxf(m1, __shfl_xor_sync(0xffffffffu, m1, 2));
    float s0 = 0.f, s1 = 0.f;
#pragma unroll
    for (int nt = 0; nt < 8; nt++) {
        float e0 = __expf(cqk[nt][0] - m0), e1 = __expf(cqk[nt][1] - m0);
        float e2 = __expf(cqk[nt][2] - m1), e3 = __expf(cqk[nt][3] - m1);
        cqk[nt][0] = e0; cqk[nt][1] = e1; cqk[nt][2] = e2; cqk[nt][3] = e3;
        s0 += e0 + e1; s1 += e2 + e3;
    }
    s0 += __shfl_xor_sync(0xffffffffu, s0, 1);
    s0 += __shfl_xor_sync(0xffffffffu, s0, 2);
    s1 += __shfl_xor_sync(0xffffffffu, s1, 1);
    s1 += __shfl_xor_sync(0xffffffffu, s1, 2);
    if (tig == 0) {
        stats[(wn * 64 + arow) * 2]         = m0;
        stats[(wn * 64 + arow) * 2 + 1]     = s0;
        stats[(wn * 64 + arow + 8) * 2]     = m1;
        stats[(wn * 64 + arow + 8) * 2 + 1] = s1;
    }
    __syncthreads();
    float om0 = stats[((wn ^ 1) * 64 + arow) * 2];
    float os0 = stats[((wn ^ 1) * 64 + arow) * 2 + 1];
    float om1 = stats[((wn ^ 1) * 64 + arow + 8) * 2];
    float os1 = stats[((wn ^ 1) * 64 + arow + 8) * 2 + 1];
    float M0 = fmaxf(m0, om0), M1 = fmaxf(m1, om1);
    float S0 = s0 * __expf(m0 - M0) + os0 * __expf(om0 - M0);
    float S1 = s1 * __expf(m1 - M1) + os1 * __expf(om1 - M1);
    float sc0 = __expf(m0 - M0) / S0;
    float sc1 = __expf(m1 - M1) / S1;
    if (wn == 0 && tig == 0) {
        g_lse[((size_t)(b * HH + h)) * SS + tq0] = M0 + __logf(S0);
        g_lse[((size_t)(b * HH + h)) * SS + tq1] = M1 + __logf(S1);
    }

    // ---- P @ V over this warp's 64-key half (K=64, 4 k16 steps), full f range (8 n-tiles)
    // A fragments pair cqk[2s] (keys j0) with cqk[2s+1] (keys j0+8) to match permuted VT.
    float oacc[8][4];
#pragma unroll
    for (int ft = 0; ft < 8; ft++)
#pragma unroll
        for (int r = 0; r < 4; r++) oacc[ft][r] = 0.f;

#pragma unroll
    for (int s = 0; s < 4; s++) {
        unsigned a0 = h2_u32(__floats2half2_rn(cqk[2 * s][0] * sc0, cqk[2 * s + 1][0] * sc0));
        unsigned a2 = h2_u32(__floats2half2_rn(cqk[2 * s][1] * sc0, cqk[2 * s + 1][1] * sc0));
        unsigned a1 = h2_u32(__floats2half2_rn(cqk[2 * s][2] * sc1, cqk[2 * s + 1][2] * sc1));
        unsigned a3 = h2_u32(__floats2half2_rn(cqk[2 * s][3] * sc1, cqk[2 * s + 1][3] * sc1));
        int pbase = wn * 64 + s * 16 + 4 * tig;
#pragma unroll
        for (int ft = 0; ft < 8; ft++) {
            uint2 Bv = *(uint2*)&VT[(ft * 8 + gID) * 136 + pbase];  // (j0,j0+8), (j0+1,j0+9)
            mma_f16(oacc[ft], a0, a1, a2, a3, Bv.x, Bv.y);
        }
    }

    // ---- sum wn partials via Dx, store fp16 outputs by original token position
    if (wn == 1) {
#pragma unroll
        for (int ft = 0; ft < 8; ft++) {
            *(float2*)&Dx[arow * 66 + ft * 8 + 2 * tig]       = make_float2(oacc[ft][0], oacc[ft][1]);
            *(float2*)&Dx[(arow + 8) * 66 + ft * 8 + 2 * tig] = make_float2(oacc[ft][2], oacc[ft][3]);
        }
    }
    __syncthreads();
    if (wn == 0) {
        __half2* o0 = g_o + (((size_t)(b * HH + h)) * SS + tq0) * 32;
        __half2* o1 = g_o + (((size_t)(b * HH + h)) * SS + tq1) * 32;
#pragma unroll
        for (int ft = 0; ft < 8; ft++) {
            float2 d0 = *(float2*)&Dx[arow * 66 + ft * 8 + 2 * tig];
            float2 d1 = *(float2*)&Dx[(arow + 8) * 66 + ft * 8 + 2 * tig];
            o0[ft * 4 + tig] = __floats2half2_rn(oacc[ft][0] + d0.x, oacc[ft][1] + d0.y);
            o1[ft * 4 + tig] = __floats2half2_rn(oacc[ft][2] + d1.x, oacc[ft][3] + d1.y);
        }
    }
}

// ==================== Kernel 4: combine hash rounds ====================
__global__ __launch_bounds__(256) void combine_kernel(float* __restrict__ out) {
    const int gw = (blockIdx.x * 256 + threadIdx.x) >> 5;
    const int l  = threadIdx.x & 31;
    const int b  = gw >> 12, t = gw & (SS - 1);

    float lg[HH];
#pragma unroll
    for (int hh = 0; hh < HH; hh++) lg[hh] = g_lse[((size_t)(b * HH + hh)) * SS + t];
    float m = lg[0];
#pragma unroll
    for (int hh = 1; hh < HH; hh++) m = fmaxf(m, lg[hh]);
    float wv[HH];
    float wsum = 0.f;
#pragma unroll
    for (int hh = 0; hh < HH; hh++) { wv[hh] = __expf(lg[hh] - m); wsum += wv[hh]; }
    float inv = 1.0f / wsum;

    float2 accv = make_float2(0.f, 0.f);
#pragma unroll
    for (int hh = 0; hh < HH; hh++) {
        float2 ov = __half22float2(g_o[((((size_t)(b * HH + hh)) * SS + t) * 32) + l]);
        float wgt = wv[hh] * inv;
        accv.x += wgt * ov.x;
        accv.y += wgt * ov.y;
    }
    ((float2*)(out + ((size_t)b * SS + t) * DD))[l] = accv;
}

// ==================== launch ====================
extern "C" void kernel_launch(void* const* d_in, const int* in_sizes, int n_in,
                              void* d_out, int out_size) {
    const float* qk  = (const float*)d_in[0];
    const float* v   = (const float*)d_in[1];
    const float* rot = (const float*)d_in[2];
    float* out = (float*)d_out;

    (void)in_sizes; (void)n_in; (void)out_size;

    const int hash_smem = 87040;   // 64*68*4 + 256*68*4
    const int attn_smem = 49920;   // tqi/tki/stats + Qsm + Ksm + VT
    cudaFuncSetAttribute(hash_kernel, cudaFuncAttributeMaxDynamicSharedMemorySize, hash_smem);
    cudaFuncSetAttribute(attn_kernel, cudaFuncAttributeMaxDynamicSharedMemorySize, attn_smem);

    hash_kernel<<<BB * (SS / 64), 256, hash_smem>>>(qk, rot);
    sort_kernel<<<BB * HH, 512>>>();
    attn_kernel<<<BB * CHK, 256, attn_smem>>>(qk, v);
    combine_kernel<<<(BB * SS) / 8, 256>>>(out);
}

// round 9
// speedup vs baseline: 2.0319x; 1.6834x over previous
#include <cuda_runtime.h>
#include <cuda_fp16.h>
#include <math.h>

// Problem constants (fixed shapes from reference)
#define BB 16
#define SS 4096
#define DD 64
#define HH 8
#define NBK 64          // buckets per hash round
#define CHK 512         // chunks per batch (HH * NBK)
#define BSZ 64          // bucket/chunk size
#define KVN 128         // keys per chunk (current + look-back)

// -------------------- device scratch (no allocation allowed) --------------------
__device__ int     g_buckets[BB * HH * SS];               // 2 MB
__device__ int     g_st[BB * HH * SS];                    // 2 MB  sorted original positions
__device__ float   g_lse[BB * HH * SS];                   // 2 MB  per-round logits (unsorted layout)
__device__ __half2 g_o[(size_t)BB * HH * SS * 32];        // 67 MB per-round outputs (fp16, unsorted)
__device__ __half2 g_qh[(size_t)BB * SS * 32];            // 8 MB  fp16 q * D^-0.5
__device__ __half2 g_kh[(size_t)BB * SS * 32];            // 8 MB  fp16 normalized k
__device__ __half2 g_vh[(size_t)BB * SS * 32];            // 8 MB  fp16 v

// -------------------- helpers --------------------
__device__ __forceinline__ unsigned h2_u32(__half2 h) {
    union { __half2 h; unsigned u; } cvt;
    cvt.h = h;
    return cvt.u;
}

__device__ __forceinline__ void mma_f16(float* c,
                                        unsigned a0, unsigned a1, unsigned a2, unsigned a3,
                                        unsigned b0, unsigned b1) {
    asm volatile("mma.sync.aligned.m16n8k16.row.col.f32.f16.f16.f32 "
                 "{%0,%1,%2,%3},{%4,%5,%6,%7},{%8,%9},{%0,%1,%2,%3};"
                 : "+f"(c[0]), "+f"(c[1]), "+f"(c[2]), "+f"(c[3])
                 : "r"(a0), "r"(a1), "r"(a2), "r"(a3), "r"(b0), "r"(b1));
}

__device__ __forceinline__ void ldsm4(unsigned& r0, unsigned& r1, unsigned& r2, unsigned& r3,
                                      unsigned addr) {
    asm volatile("ldmatrix.sync.aligned.m8n8.x4.shared.b16 {%0,%1,%2,%3}, [%4];"
                 : "=r"(r0), "=r"(r1), "=r"(r2), "=r"(r3) : "r"(addr));
}

__device__ __forceinline__ void ldsm4t(unsigned& r0, unsigned& r1, unsigned& r2, unsigned& r3,
                                       unsigned addr) {
    asm volatile("ldmatrix.sync.aligned.m8n8.x4.trans.shared.b16 {%0,%1,%2,%3}, [%4];"
                 : "=r"(r0), "=r"(r1), "=r"(r2), "=r"(r3) : "r"(addr));
}

__device__ __forceinline__ void cp16(unsigned dst, const void* src) {
    asm volatile("cp.async.cg.shared.global [%0], [%1], 16;" :: "r"(dst), "l"(src) : "memory");
}

// ==================== Kernel 0: precompute fp16 q (scaled), k (normalized), v ====================
// grid = BB*SS/64 = 1024 CTAs, 256 threads; warp handles 8 token rows.
__global__ __launch_bounds__(256) void prep_kernel(const float* __restrict__ qk,
                                                   const float* __restrict__ v) {
    const int w = threadIdx.x >> 5, l = threadIdx.x & 31;
    const int gi0 = blockIdx.x * 64 + w * 8;
    for (int r = 0; r < 8; r++) {
        int gi = gi0 + r;
        float2 kv = ((const float2*)(qk + (size_t)gi * DD))[l];
        float ssq = kv.x * kv.x + kv.y * kv.y;
#pragma unroll
        for (int o = 16; o; o >>= 1) ssq += __shfl_xor_sync(0xffffffffu, ssq, o);
        float inv = 1.0f / fmaxf(sqrtf(ssq), 1e-12f);
        g_kh[(size_t)gi * 32 + l] = __floats2half2_rn(kv.x * inv, kv.y * inv);
        g_qh[(size_t)gi * 32 + l] = __floats2half2_rn(kv.x * 0.125f, kv.y * 0.125f);
        float2 vv = ((const float2*)(v + (size_t)gi * DD))[l];
        g_vh[(size_t)gi * 32 + l] = __floats2half2_rn(vv.x, vv.y);
    }
}

// ==================== Kernel 1: LSH hashing (fp32 — argmax is discrete) ====================
__global__ __launch_bounds__(256, 2) void hash_kernel(const float* __restrict__ qk,
                                                      const float* __restrict__ rot) {
    extern __shared__ float sm[];
    float* qT  = sm;              // 64*68 floats
    float* big = sm + 64 * 68;    // max(64*260, 256*68) = 17408 floats

    const int blk  = blockIdx.x;
    const int b    = blk >> 6;
    const int t0   = (blk & 63) * 64;
    const int tid  = threadIdx.x;
    const int w    = tid >> 5, l = tid & 31;

    {
        const float4* rg = (const float4*)rot;
        for (int i4 = tid; i4 < 64 * 64; i4 += 256) {
            int f = i4 >> 6, o4 = i4 & 63;
            *(float4*)&big[f * 260 + o4 * 4] = rg[i4];
        }
    }
    for (int r = 0; r < 8; r++) {
        int i = w * 8 + r;
        float2 qv = ((const float2*)(qk + ((size_t)b * SS + t0 + i) * DD))[l];
        qT[(2 * l) * 68 + i]     = qv.x;
        qT[(2 * l + 1) * 68 + i] = qv.y;
    }
    __syncthreads();

    const int rt = tid >> 4, ct = tid & 15;
    float acc[4][16];
#pragma unroll
    for (int r = 0; r < 4; r++)
#pragma unroll
        for (int c = 0; c < 16; c++) acc[r][c] = 0.f;

    const float4* qT4 = (const float4*)qT;   // stride 17
    const float4* rt4 = (const float4*)big;  // stride 65
#pragma unroll 4
    for (int f = 0; f < 64; f++) {
        float4 q = qT4[f * 17 + rt];
        float qa[4] = {q.x, q.y, q.z, q.w};
#pragma unroll
        for (int g = 0; g < 4; g++) {
            float4 rv = rt4[f * 65 + g * 16 + ct];
            float ra[4] = {rv.x, rv.y, rv.z, rv.w};
#pragma unroll
            for (int r = 0; r < 4; r++)
#pragma unroll
                for (int c = 0; c < 4; c++)
                    acc[r][g * 4 + c] += qa[r] * ra[c];
        }
    }
    __syncthreads();

    float* dsH = big;
#pragma unroll
    for (int g = 0; g < 4; g++)
#pragma unroll
        for (int c = 0; c < 4; c++) {
            int o = g * 64 + ct * 4 + c;
            *(float4*)&dsH[o * 68 + rt * 4] =
                make_float4(acc[0][g * 4 + c], acc[1][g * 4 + c], acc[2][g * 4 + c], acc[3][g * 4 + c]);
        }
    __syncthreads();

    for (int p = tid; p < 512; p += 256) {
        int t = p & 63, hh = p >> 6;
        const float* dv = &dsH[(hh * 32) * 68 + t];
        float best = dv[0];
        int bi = 0;
#pragma unroll
        for (int j = 1; j < 32; j++) { float vv = dv[j * 68];  if (vv > best) { best = vv; bi = j; } }
#pragma unroll
        for (int j = 0; j < 32; j++) { float vv = -dv[j * 68]; if (vv > best) { best = vv; bi = 32 + j; } }
        g_buckets[((size_t)(b * HH + hh)) * SS + t0 + t] = bi;
    }
}

// ==================== Kernel 2: stable counting sort per (b,h) ====================
__global__ __launch_bounds__(512) void sort_kernel() {
    __shared__ int hist[16][64];
    __shared__ int run[16][64];
    __shared__ int totals[64];
    __shared__ int bstart[64];

    const int bh  = blockIdx.x;
    const int* bk = g_buckets + (size_t)bh * SS;
    int* dst      = g_st + (size_t)bh * SS;
    const int tid = threadIdx.x, w = tid >> 5, l = tid & 31;

    for (int i = tid; i < 1024; i += 512) ((int*)hist)[i] = 0;
    __syncthreads();

    for (int r = 0; r < 8; r++) {
        int t = w * 256 + r * 32 + l;
        int vv = bk[t];
        unsigned mask = __match_any_sync(0xffffffffu, vv);
        if (l == (int)(__ffs(mask) - 1)) hist[w][vv] += __popc(mask);
        __syncwarp();
    }
    __syncthreads();

    if (tid < 64) {
        int s = 0;
        for (int ww = 0; ww < 16; ww++) { int tmp = hist[ww][tid]; hist[ww][tid] = s; s += tmp; }
        totals[tid] = s;
    }
    __syncthreads();
    if (tid == 0) {
        int s = 0;
        for (int vv = 0; vv < 64; vv++) { bstart[vv] = s; s += totals[vv]; }
    }
    __syncthreads();
    for (int i = tid; i < 1024; i += 512) {
        int ww = i >> 6, vv = i & 63;
        run[ww][vv] = bstart[vv] + hist[ww][vv];
    }
    __syncthreads();

    for (int r = 0; r < 8; r++) {
        int t = w * 256 + r * 32 + l;
        int vv = bk[t];
        unsigned mask = __match_any_sync(0xffffffffu, vv);
        int rank = __popc(mask & ((1u << l) - 1u));
        int base = run[w][vv];
        __syncwarp();
        if (l == (int)(__ffs(mask) - 1)) run[w][vv] = base + __popc(mask);
        __syncwarp();
        dst[base + rank] = t;
    }
}

// ==================== Kernel 3: chunked attention (cp.async + ldmatrix + fp16 mma) ====================
// grid = BB*CHK = 8192 CTAs, 256 threads (8 warps), 47872B smem, 3 CTAs/SM.
// Rows are raw 128B fp16 rows from prep; stride 144B (conflict-free for 16B-chunk column reads).
__global__ __launch_bounds__(256, 3) void attn_kernel() {
    extern __shared__ char smc[];
    int*    tqi   = (int*)smc;                  // 64 ints
    int*    tki   = (int*)(smc + 256);          // 128 ints
    float*  stats = (float*)(smc + 768);        // 256 floats: [wn*64+row]*2 -> {m,s}
    __half* Qsm   = (__half*)(smc + 1792);      // 64  x 144B
    __half* Ksm   = (__half*)(smc + 11008);     // 128 x 144B
    __half* Vsm   = (__half*)(smc + 29440);     // 128 x 144B (row-major)
    float*  Dx    = (float*)(smc + 1792);       // 64 x 66 (aliases Qsm/Ksm after QK)

    const int blk = blockIdx.x;
    const int b = blk >> 9, c = blk & 511;
    const int h  = c >> 6;
    const int cp = (c + 511) & 511;
    const int hp = cp >> 6;
    const int tid = threadIdx.x, w = tid >> 5, l = tid & 31;
    const int gID = l >> 2, tig = l & 3;
    const int wm = w & 3, wn = w >> 2;
    const int arow = wm * 16 + gID;

    if (tid < 64) {
        int t = g_st[((size_t)(b * HH + h)) * SS + (c & 63) * 64 + tid];
        tqi[tid] = t;
        tki[tid] = t;
    } else if (tid < 128) {
        int i = tid - 64;
        tki[64 + i] = g_st[((size_t)(b * HH + hp)) * SS + (cp & 63) * 64 + i];
    }
    __syncthreads();

    // ---- gather via cp.async: 16B chunks, 8 per 128B row
    {
        unsigned q_u32 = (unsigned)__cvta_generic_to_shared(Qsm);
        unsigned k_u32 = (unsigned)__cvta_generic_to_shared(Ksm);
        unsigned v_u32 = (unsigned)__cvta_generic_to_shared(Vsm);
        const char* qh = (const char*)g_qh + (size_t)b * SS * 128;
        const char* kh = (const char*)g_kh + (size_t)b * SS * 128;
        const char* vh = (const char*)g_vh + (size_t)b * SS * 128;
#pragma unroll
        for (int it = 0; it < 2; it++) {           // 64 q rows
            int slot = tid + it * 256;
            int row = slot >> 3, ch = slot & 7;
            cp16(q_u32 + row * 144 + ch * 16, qh + (size_t)tqi[row] * 128 + ch * 16);
        }
#pragma unroll
        for (int it = 0; it < 4; it++) {           // 128 k rows
            int slot = tid + it * 256;
            int row = slot >> 3, ch = slot & 7;
            cp16(k_u32 + row * 144 + ch * 16, kh + (size_t)tki[row] * 128 + ch * 16);
        }
#pragma unroll
        for (int it = 0; it < 4; it++) {           // 128 v rows
            int slot = tid + it * 256;
            int row = slot >> 3, ch = slot & 7;
            cp16(v_u32 + row * 144 + ch * 16, vh + (size_t)tki[row] * 128 + ch * 16);
        }
        asm volatile("cp.async.commit_group;" ::: "memory");
        asm volatile("cp.async.wait_group 0;" ::: "memory");
    }
    __syncthreads();

    // ---- ldmatrix lane addressing: thread c supplies row (c&7) + 8*((c>>3)&1), col-shift 8*((c>>4)&1)
    const int lrow = (l & 7) + ((l >> 3) & 1) * 8;
    const int lcsh = ((l >> 4) & 1) * 16;          // bytes
    const unsigned qfrag = (unsigned)__cvta_generic_to_shared(Qsm) + (wm * 16 + lrow) * 144 + lcsh;
    const unsigned kfragb = (unsigned)__cvta_generic_to_shared(Ksm) + (wn * 64 + lrow) * 144 + lcsh;
    const unsigned vfragb = (unsigned)__cvta_generic_to_shared(Vsm) + (wn * 64 + lrow) * 144 + lcsh;

    // ---- QK^T via fp16 mma (K=64: 4 k16 steps; 8 n-tiles as 4 pairs)
    float cqk[8][4];
#pragma unroll
    for (int nt = 0; nt < 8; nt++)
#pragma unroll
        for (int r = 0; r < 4; r++) cqk[nt][r] = 0.f;

#pragma unroll
    for (int s = 0; s < 4; s++) {
        unsigned a0, a1, a2, a3;
        ldsm4(a0, a1, a2, a3, qfrag + s * 32);
#pragma unroll
        for (int p = 0; p < 4; p++) {
            unsigned b00, b01, b10, b11;   // tiles: (ntE,kL),(ntO,kL),(ntE,kH),(ntO,kH)
            ldsm4(b00, b01, b10, b11, kfragb + p * 16 * 144 + s * 32);
            mma_f16(cqk[2 * p],     a0, a1, a2, a3, b00, b10);
            mma_f16(cqk[2 * p + 1], a0, a1, a2, a3, b01, b11);
        }
    }

    // ---- self-mask (standard C layout: cols nt*8 + 2tig + {0,1}; rows gID / gID+8)
    const int tq0 = tqi[arow], tq1 = tqi[arow + 8];
#pragma unroll
    for (int nt = 0; nt < 8; nt++) {
        int2 kk = *(int2*)&tki[wn * 64 + nt * 8 + 2 * tig];
        if (kk.x == tq0) cqk[nt][0] = -5e4f;
        if (kk.y == tq0) cqk[nt][1] = -5e4f;
        if (kk.x == tq1) cqk[nt][2] = -5e4f;
        if (kk.y == tq1) cqk[nt][3] = -5e4f;
    }

    // ---- register softmax: per-row partial (m, s) within warp half, merge across wn
    float m0 = -3.4e38f, m1 = -3.4e38f;
#pragma unroll
    for (int nt = 0; nt < 8; nt++) {
        m0 = fmaxf(m0, fmaxf(cqk[nt][0], cqk[nt][1]));
        m1 = fmaxf(m1, fmaxf(cqk[nt][2], cqk[nt][3]));
    }
    m0 = fmaxf(m0, __shfl_xor_sync(0xffffffffu, m0, 1));
    m0 = fmaxf(m0, __shfl_xor_sync(0xffffffffu, m0, 2));
    m1 = fmaxf(m1, __shfl_xor_sync(0xffffffffu, m1, 1));
    m1 = fmaxf(m1, __shfl_xor_sync(0xffffffffu, m1, 2));
    float s0 = 0.f, s1 = 0.f;
#pragma unroll
    for (int nt = 0; nt < 8; nt++) {
        float e0 = __expf(cqk[nt][0] - m0), e1 = __expf(cqk[nt][1] - m0);
        float e2 = __expf(cqk[nt][2] - m1), e3 = __expf(cqk[nt][3] - m1);
        cqk[nt][0] = e0; cqk[nt][1] = e1; cqk[nt][2] = e2; cqk[nt][3] = e3;
        s0 += e0 + e1; s1 += e2 + e3;
    }
    s0 += __shfl_xor_sync(0xffffffffu, s0, 1);
    s0 += __shfl_xor_sync(0xffffffffu, s0, 2);
    s1 += __shfl_xor_sync(0xffffffffu, s1, 1);
    s1 += __shfl_xor_sync(0xffffffffu, s1, 2);
    if (tig == 0) {
        stats[(wn * 64 + arow) * 2]         = m0;
        stats[(wn * 64 + arow) * 2 + 1]     = s0;
        stats[(wn * 64 + arow + 8) * 2]     = m1;
        stats[(wn * 64 + arow + 8) * 2 + 1] = s1;
    }
    __syncthreads();
    float om0 = stats[((wn ^ 1) * 64 + arow) * 2];
    float os0 = stats[((wn ^ 1) * 64 + arow) * 2 + 1];
    float om1 = stats[((wn ^ 1) * 64 + arow + 8) * 2];
    float os1 = stats[((wn ^ 1) * 64 + arow + 8) * 2 + 1];
    float M0 = fmaxf(m0, om0), M1 = fmaxf(m1, om1);
    float S0 = s0 * __expf(m0 - M0) + os0 * __expf(om0 - M0);
    float S1 = s1 * __expf(m1 - M1) + os1 * __expf(om1 - M1);
    float sc0 = __expf(m0 - M0) / S0;
    float sc1 = __expf(m1 - M1) / S1;
    if (wn == 0 && tig == 0) {
        g_lse[((size_t)(b * HH + h)) * SS + tq0] = M0 + __logf(S0);
        g_lse[((size_t)(b * HH + h)) * SS + tq1] = M1 + __logf(S1);
    }

    // ---- P @ V over this warp's 64-key half; B via ldmatrix.trans from row-major Vsm
    float oacc[8][4];
#pragma unroll
    for (int ft = 0; ft < 8; ft++)
#pragma unroll
        for (int r = 0; r < 4; r++) oacc[ft][r] = 0.f;

#pragma unroll
    for (int s = 0; s < 4; s++) {
        // standard A fragment: a0=(gID, k 2tig..)=cqk[2s][0..1], a2=(gID, k+8)=cqk[2s+1][0..1]
        unsigned a0 = h2_u32(__floats2half2_rn(cqk[2 * s][0] * sc0, cqk[2 * s][1] * sc0));
        unsigned a1 = h2_u32(__floats2half2_rn(cqk[2 * s][2] * sc1, cqk[2 * s][3] * sc1));
        unsigned a2 = h2_u32(__floats2half2_rn(cqk[2 * s + 1][0] * sc0, cqk[2 * s + 1][1] * sc0));
        unsigned a3 = h2_u32(__floats2half2_rn(cqk[2 * s + 1][2] * sc1, cqk[2 * s + 1][3] * sc1));
#pragma unroll
        for (int t = 0; t < 4; t++) {
            unsigned r0, r1, r2, r3;       // tiles: (jL,fE)=b0 ftE, (jH,fE)=b1 ftE, (jL,fO), (jH,fO)
            ldsm4t(r0, r1, r2, r3, vfragb + s * 16 * 144 + t * 32);
            mma_f16(oacc[2 * t],     a0, a1, a2, a3, r0, r1);
            mma_f16(oacc[2 * t + 1], a0, a1, a2, a3, r2, r3);
        }
    }

    // ---- sum wn partials via Dx, store fp16 outputs by original token position
    if (wn == 1) {
#pragma unroll
        for (int ft = 0; ft < 8; ft++) {
            *(float2*)&Dx[arow * 66 + ft * 8 + 2 * tig]       = make_float2(oacc[ft][0], oacc[ft][1]);
            *(float2*)&Dx[(arow + 8) * 66 + ft * 8 + 2 * tig] = make_float2(oacc[ft][2], oacc[ft][3]);
        }
    }
    __syncthreads();
    if (wn == 0) {
        __half2* o0 = g_o + (((size_t)(b * HH + h)) * SS + tq0) * 32;
        __half2* o1 = g_o + (((size_t)(b * HH + h)) * SS + tq1) * 32;
#pragma unroll
        for (int ft = 0; ft < 8; ft++) {
            float2 d0 = *(float2*)&Dx[arow * 66 + ft * 8 + 2 * tig];
            float2 d1 = *(float2*)&Dx[(arow + 8) * 66 + ft * 8 + 2 * tig];
            o0[ft * 4 + tig] = __floats2half2_rn(oacc[ft][0] + d0.x, oacc[ft][1] + d0.y);
            o1[ft * 4 + tig] = __floats2half2_rn(oacc[ft][2] + d1.x, oacc[ft][3] + d1.y);
        }
    }
}

// ==================== Kernel 4: combine hash rounds ====================
__global__ __launch_bounds__(256) void combine_kernel(float* __restrict__ out) {
    const int gw = (blockIdx.x * 256 + threadIdx.x) >> 5;
    const int l  = threadIdx.x & 31;
    const int b  = gw >> 12, t = gw & (SS - 1);

    float lg[HH];
#pragma unroll
    for (int hh = 0; hh < HH; hh++) lg[hh] = g_lse[((size_t)(b * HH + hh)) * SS + t];
    float m = lg[0];
#pragma unroll
    for (int hh = 1; hh < HH; hh++) m = fmaxf(m, lg[hh]);
    float wv[HH];
    float wsum = 0.f;
#pragma unroll
    for (int hh = 0; hh < HH; hh++) { wv[hh] = __expf(lg[hh] - m); wsum += wv[hh]; }
    float inv = 1.0f / wsum;

    float2 accv = make_float2(0.f, 0.f);
#pragma unroll
    for (int hh = 0; hh < HH; hh++) {
        float2 ov = __half22float2(g_o[((((size_t)(b * HH + hh)) * SS + t) * 32) + l]);
        float wgt = wv[hh] * inv;
        accv.x += wgt * ov.x;
        accv.y += wgt * ov.y;
    }
    ((float2*)(out + ((size_t)b * SS + t) * DD))[l] = accv;
}

// ==================== launch ====================
extern "C" void kernel_launch(void* const* d_in, const int* in_sizes, int n_in,
                              void* d_out, int out_size) {
    const float* qk  = (const float*)d_in[0];
    const float* v   = (const float*)d_in[1];
    const float* rot = (const float*)d_in[2];
    float* out = (float*)d_out;

    (void)in_sizes; (void)n_in; (void)out_size;

    const int hash_smem = 87040;   // 64*68*4 + 256*68*4
    const int attn_smem = 47872;   // tqi/tki/stats + Qsm(64x144) + Ksm(128x144) + Vsm(128x144)
    cudaFuncSetAttribute(hash_kernel, cudaFuncAttributeMaxDynamicSharedMemorySize, hash_smem);
    cudaFuncSetAttribute(attn_kernel, cudaFuncAttributeMaxDynamicSharedMemorySize, attn_smem);

    prep_kernel<<<BB * (SS / 64), 256>>>(qk, v);
    hash_kernel<<<BB * (SS / 64), 256, hash_smem>>>(qk, rot);
    sort_kernel<<<BB * HH, 512>>>();
    attn_kernel<<<BB * CHK, 256, attn_smem>>>();
    combine_kernel<<<(BB * SS) / 8, 256>>>(out);
}

// round 10
// speedup vs baseline: 2.2606x; 1.1126x over previous
#include <cuda_runtime.h>
#include <cuda_fp16.h>
#include <math.h>

// Problem constants (fixed shapes from reference)
#define BB 16
#define SS 4096
#define DD 64
#define HH 8
#define NBK 64          // buckets per hash round
#define CHK 512         // chunks per batch (HH * NBK)
#define BSZ 64          // bucket/chunk size
#define KVN 128         // keys per chunk (current + look-back)

// -------------------- device scratch (no allocation allowed) --------------------
__device__ int     g_buckets[BB * HH * SS];               // 2 MB
__device__ int     g_st[BB * HH * SS];                    // 2 MB  sorted original positions
__device__ float   g_lse[BB * HH * SS];                   // 2 MB  per-round logits (unsorted layout)
__device__ __half2 g_o[(size_t)BB * HH * SS * 32];        // 67 MB per-round outputs (fp16, unsorted)
__device__ __half2 g_qh[(size_t)BB * SS * 32];            // 8 MB  fp16 q * D^-0.5
__device__ __half2 g_kh[(size_t)BB * SS * 32];            // 8 MB  fp16 normalized k
__device__ __half2 g_vh[(size_t)BB * SS * 32];            // 8 MB  fp16 v

// -------------------- helpers --------------------
__device__ __forceinline__ unsigned h2_u32(__half2 h) {
    union { __half2 h; unsigned u; } cvt;
    cvt.h = h;
    return cvt.u;
}

__device__ __forceinline__ void mma_f16(float* c,
                                        unsigned a0, unsigned a1, unsigned a2, unsigned a3,
                                        unsigned b0, unsigned b1) {
    asm volatile("mma.sync.aligned.m16n8k16.row.col.f32.f16.f16.f32 "
                 "{%0,%1,%2,%3},{%4,%5,%6,%7},{%8,%9},{%0,%1,%2,%3};"
                 : "+f"(c[0]), "+f"(c[1]), "+f"(c[2]), "+f"(c[3])
                 : "r"(a0), "r"(a1), "r"(a2), "r"(a3), "r"(b0), "r"(b1));
}

__device__ __forceinline__ void ldsm4(unsigned& r0, unsigned& r1, unsigned& r2, unsigned& r3,
                                      unsigned addr) {
    asm volatile("ldmatrix.sync.aligned.m8n8.x4.shared.b16 {%0,%1,%2,%3}, [%4];"
                 : "=r"(r0), "=r"(r1), "=r"(r2), "=r"(r3) : "r"(addr));
}

__device__ __forceinline__ void ldsm4t(unsigned& r0, unsigned& r1, unsigned& r2, unsigned& r3,
                                       unsigned addr) {
    asm volatile("ldmatrix.sync.aligned.m8n8.x4.trans.shared.b16 {%0,%1,%2,%3}, [%4];"
                 : "=r"(r0), "=r"(r1), "=r"(r2), "=r"(r3) : "r"(addr));
}

__device__ __forceinline__ void cp16(unsigned dst, const void* src) {
    asm volatile("cp.async.cg.shared.global [%0], [%1], 16;" :: "r"(dst), "l"(src) : "memory");
}

// packed f32x2 helpers (Blackwell)
__device__ __forceinline__ unsigned long long pack2(float x, float y) {
    unsigned long long r;
    asm("mov.b64 %0, {%1, %2};" : "=l"(r) : "f"(x), "f"(y));
    return r;
}
__device__ __forceinline__ void unpack2(float& x, float& y, unsigned long long p) {
    asm("mov.b64 {%0, %1}, %2;" : "=f"(x), "=f"(y) : "l"(p));
}
__device__ __forceinline__ void fma2(unsigned long long& d, unsigned long long a, unsigned long long b) {
    asm("fma.rn.f32x2 %0, %1, %2, %0;" : "+l"(d) : "l"(a), "l"(b));
}

// pair barrier: warps {wm, wm+4} (64 threads), ids 1..4
#define BARP(id) asm volatile("bar.sync %0, 64;" :: "r"(id) : "memory")

// ==================== Kernel 1: LSH hashing (fp32 f32x2) + fused fp16 prep ====================
// grid = BB * (SS/64) = 1024 CTAs, 256 threads.
__global__ __launch_bounds__(256, 2) void hash_kernel(const float* __restrict__ qk,
                                                      const float* __restrict__ v,
                                                      const float* __restrict__ rot) {
    extern __shared__ float sm[];
    float* qT  = sm;              // 64*68 floats
    float* big = sm + 64 * 68;    // max(64*260, 256*68) = 17408 floats

    const int blk  = blockIdx.x;
    const int b    = blk >> 6;
    const int t0   = (blk & 63) * 64;
    const int tid  = threadIdx.x;
    const int w    = tid >> 5, l = tid & 31;

    {
        const float4* rg = (const float4*)rot;
        for (int i4 = tid; i4 < 64 * 64; i4 += 256) {
            int f = i4 >> 6, o4 = i4 & 63;
            *(float4*)&big[f * 260 + o4 * 4] = rg[i4];
        }
    }
    // q tile load (transposed into qT) + fused prep: qh, kh, vh
    for (int r = 0; r < 8; r++) {
        int i = w * 8 + r;
        size_t gi = (size_t)b * SS + t0 + i;
        float2 qv = ((const float2*)(qk + gi * DD))[l];
        qT[(2 * l) * 68 + i]     = qv.x;
        qT[(2 * l + 1) * 68 + i] = qv.y;
        float ssq = qv.x * qv.x + qv.y * qv.y;
#pragma unroll
        for (int o = 16; o; o >>= 1) ssq += __shfl_xor_sync(0xffffffffu, ssq, o);
        float inv = 1.0f / fmaxf(sqrtf(ssq), 1e-12f);
        g_kh[gi * 32 + l] = __floats2half2_rn(qv.x * inv, qv.y * inv);
        g_qh[gi * 32 + l] = __floats2half2_rn(qv.x * 0.125f, qv.y * 0.125f);
        float2 vv = ((const float2*)(v + gi * DD))[l];
        g_vh[gi * 32 + l] = __floats2half2_rn(vv.x, vv.y);
    }
    __syncthreads();

    const int rt = tid >> 4, ct = tid & 15;
    unsigned long long acc2[4][8];   // [row][pair]: pair p packs output cols (g*4+2p, g*4+2p+1) for g=p>>1
#pragma unroll
    for (int r = 0; r < 4; r++)
#pragma unroll
        for (int p = 0; p < 8; p++) acc2[r][p] = pack2(0.f, 0.f);

    const float4* qT4 = (const float4*)qT;   // stride 17
    const float4* rt4 = (const float4*)big;  // stride 65
#pragma unroll 4
    for (int f = 0; f < 64; f++) {
        float4 q = qT4[f * 17 + rt];
        unsigned long long qq[4];
        qq[0] = pack2(q.x, q.x); qq[1] = pack2(q.y, q.y);
        qq[2] = pack2(q.z, q.z); qq[3] = pack2(q.w, q.w);
#pragma unroll
        for (int g = 0; g < 4; g++) {
            float4 rv = rt4[f * 65 + g * 16 + ct];
            unsigned long long r0 = pack2(rv.x, rv.y);
            unsigned long long r1 = pack2(rv.z, rv.w);
#pragma unroll
            for (int r = 0; r < 4; r++) {
                fma2(acc2[r][g * 2],     qq[r], r0);
                fma2(acc2[r][g * 2 + 1], qq[r], r1);
            }
        }
    }
    // unpack
    float acc[4][16];
#pragma unroll
    for (int r = 0; r < 4; r++)
#pragma unroll
        for (int p = 0; p < 8; p++)
            unpack2(acc[r][p * 2], acc[r][p * 2 + 1], acc2[r][p]);
    __syncthreads();   // rot dead, reuse region as dsH[o][t] stride 68

    float* dsH = big;
#pragma unroll
    for (int g = 0; g < 4; g++)
#pragma unroll
        for (int c = 0; c < 4; c++) {
            int o = g * 64 + ct * 4 + c;
            *(float4*)&dsH[o * 68 + rt * 4] =
                make_float4(acc[0][g * 4 + c], acc[1][g * 4 + c], acc[2][g * 4 + c], acc[3][g * 4 + c]);
        }
    __syncthreads();

    for (int p = tid; p < 512; p += 256) {
        int t = p & 63, hh = p >> 6;
        const float* dv = &dsH[(hh * 32) * 68 + t];
        float best = dv[0];
        int bi = 0;
#pragma unroll
        for (int j = 1; j < 32; j++) { float vv = dv[j * 68];  if (vv > best) { best = vv; bi = j; } }
#pragma unroll
        for (int j = 0; j < 32; j++) { float vv = -dv[j * 68]; if (vv > best) { best = vv; bi = 32 + j; } }
        g_buckets[((size_t)(b * HH + hh)) * SS + t0 + t] = bi;
    }
}

// ==================== Kernel 2: stable counting sort per (b,h) ====================
__global__ __launch_bounds__(512) void sort_kernel() {
    __shared__ int hist[16][64];
    __shared__ int run[16][64];
    __shared__ int totals[64];
    __shared__ int bstart[64];

    const int bh  = blockIdx.x;
    const int* bk = g_buckets + (size_t)bh * SS;
    int* dst      = g_st + (size_t)bh * SS;
    const int tid = threadIdx.x, w = tid >> 5, l = tid & 31;

    for (int i = tid; i < 1024; i += 512) ((int*)hist)[i] = 0;
    __syncthreads();

    for (int r = 0; r < 8; r++) {
        int t = w * 256 + r * 32 + l;
        int vv = bk[t];
        unsigned mask = __match_any_sync(0xffffffffu, vv);
        if (l == (int)(__ffs(mask) - 1)) hist[w][vv] += __popc(mask);
        __syncwarp();
    }
    __syncthreads();

    if (tid < 64) {
        int s = 0;
        for (int ww = 0; ww < 16; ww++) { int tmp = hist[ww][tid]; hist[ww][tid] = s; s += tmp; }
        totals[tid] = s;
    }
    __syncthreads();
    if (tid == 0) {
        int s = 0;
        for (int vv = 0; vv < 64; vv++) { bstart[vv] = s; s += totals[vv]; }
    }
    __syncthreads();
    for (int i = tid; i < 1024; i += 512) {
        int ww = i >> 6, vv = i & 63;
        run[ww][vv] = bstart[vv] + hist[ww][vv];
    }
    __syncthreads();

    for (int r = 0; r < 8; r++) {
        int t = w * 256 + r * 32 + l;
        int vv = bk[t];
        unsigned mask = __match_any_sync(0xffffffffu, vv);
        int rank = __popc(mask & ((1u << l) - 1u));
        int base = run[w][vv];
        __syncwarp();
        if (l == (int)(__ffs(mask) - 1)) run[w][vv] = base + __popc(mask);
        __syncwarp();
        dst[base + rank] = t;
    }
}

// ==================== Kernel 3: chunked attention (cp.async + ldmatrix + fp16 mma) ====================
// grid = BB*CHK = 8192 CTAs, 256 threads (8 warps), 57088B smem, 3 CTAs/SM.
// Pair barriers (wm) replace full syncs after QK; Dx is a dedicated fp16 buffer.
__global__ __launch_bounds__(256, 3) void attn_kernel() {
    extern __shared__ char smc[];
    int*    tqi   = (int*)smc;                  // 64 ints
    int*    tki   = (int*)(smc + 256);          // 128 ints
    float*  stats = (float*)(smc + 768);        // 256 floats: [wn*64+row]*2 -> {m,s}
    __half* Qsm   = (__half*)(smc + 1792);      // 64  x 144B
    __half* Ksm   = (__half*)(smc + 11008);     // 128 x 144B
    __half* Vsm   = (__half*)(smc + 29440);     // 128 x 144B (row-major)
    __half* Dxh   = (__half*)(smc + 47872);     // 64 x 144B (72-half rows), fp16 PV partials

    const int blk = blockIdx.x;
    const int b = blk >> 9, c = blk & 511;
    const int h  = c >> 6;
    const int cp = (c + 511) & 511;
    const int hp = cp >> 6;
    const int tid = threadIdx.x, w = tid >> 5, l = tid & 31;
    const int gID = l >> 2, tig = l & 3;
    const int wm = w & 3, wn = w >> 2;
    const int arow = wm * 16 + gID;

    if (tid < 64) {
        int t = g_st[((size_t)(b * HH + h)) * SS + (c & 63) * 64 + tid];
        tqi[tid] = t;
        tki[tid] = t;
    } else if (tid < 128) {
        int i = tid - 64;
        tki[64 + i] = g_st[((size_t)(b * HH + hp)) * SS + (cp & 63) * 64 + i];
    }
    __syncthreads();

    // ---- gather via cp.async: 16B chunks, 8 per 128B row
    {
        unsigned q_u32 = (unsigned)__cvta_generic_to_shared(Qsm);
        unsigned k_u32 = (unsigned)__cvta_generic_to_shared(Ksm);
        unsigned v_u32 = (unsigned)__cvta_generic_to_shared(Vsm);
        const char* qh = (const char*)g_qh + (size_t)b * SS * 128;
        const char* kh = (const char*)g_kh + (size_t)b * SS * 128;
        const char* vh = (const char*)g_vh + (size_t)b * SS * 128;
#pragma unroll
        for (int it = 0; it < 2; it++) {           // 64 q rows
            int slot = tid + it * 256;
            int row = slot >> 3, ch = slot & 7;
            cp16(q_u32 + row * 144 + ch * 16, qh + (size_t)tqi[row] * 128 + ch * 16);
        }
#pragma unroll
        for (int it = 0; it < 4; it++) {           // 128 k rows
            int slot = tid + it * 256;
            int row = slot >> 3, ch = slot & 7;
            cp16(k_u32 + row * 144 + ch * 16, kh + (size_t)tki[row] * 128 + ch * 16);
        }
#pragma unroll
        for (int it = 0; it < 4; it++) {           // 128 v rows
            int slot = tid + it * 256;
            int row = slot >> 3, ch = slot & 7;
            cp16(v_u32 + row * 144 + ch * 16, vh + (size_t)tki[row] * 128 + ch * 16);
        }
        asm volatile("cp.async.commit_group;" ::: "memory");
        asm volatile("cp.async.wait_group 0;" ::: "memory");
    }
    __syncthreads();

    // ---- ldmatrix lane addressing
    const int lrow = (l & 7) + ((l >> 3) & 1) * 8;
    const int lcsh = ((l >> 4) & 1) * 16;          // bytes
    const unsigned qfrag = (unsigned)__cvta_generic_to_shared(Qsm) + (wm * 16 + lrow) * 144 + lcsh;
    const unsigned kfragb = (unsigned)__cvta_generic_to_shared(Ksm) + (wn * 64 + lrow) * 144 + lcsh;
    const unsigned vfragb = (unsigned)__cvta_generic_to_shared(Vsm) + (wn * 64 + lrow) * 144 + lcsh;

    // ---- QK^T via fp16 mma (K=64: 4 k16 steps; 8 n-tiles as 4 pairs)
    float cqk[8][4];
#pragma unroll
    for (int nt = 0; nt < 8; nt++)
#pragma unroll
        for (int r = 0; r < 4; r++) cqk[nt][r] = 0.f;

#pragma unroll
    for (int s = 0; s < 4; s++) {
        unsigned a0, a1, a2, a3;
        ldsm4(a0, a1, a2, a3, qfrag + s * 32);
#pragma unroll
        for (int p = 0; p < 4; p++) {
            unsigned b00, b01, b10, b11;
            ldsm4(b00, b01, b10, b11, kfragb + p * 16 * 144 + s * 32);
            mma_f16(cqk[2 * p],     a0, a1, a2, a3, b00, b10);
            mma_f16(cqk[2 * p + 1], a0, a1, a2, a3, b01, b11);
        }
    }

    // ---- self-mask
    const int tq0 = tqi[arow], tq1 = tqi[arow + 8];
#pragma unroll
    for (int nt = 0; nt < 8; nt++) {
        int2 kk = *(int2*)&tki[wn * 64 + nt * 8 + 2 * tig];
        if (kk.x == tq0) cqk[nt][0] = -5e4f;
        if (kk.y == tq0) cqk[nt][1] = -5e4f;
        if (kk.x == tq1) cqk[nt][2] = -5e4f;
        if (kk.y == tq1) cqk[nt][3] = -5e4f;
    }

    // ---- register softmax: per-row partial (m, s), merge across wn via pair barrier
    float m0 = -3.4e38f, m1 = -3.4e38f;
#pragma unroll
    for (int nt = 0; nt < 8; nt++) {
        m0 = fmaxf(m0, fmaxf(cqk[nt][0], cqk[nt][1]));
        m1 = fmaxf(m1, fmaxf(cqk[nt][2], cqk[nt][3]));
    }
    m0 = fmaxf(m0, __shfl_xor_sync(0xffffffffu, m0, 1));
    m0 = fmaxf(m0, __shfl_xor_sync(0xffffffffu, m0, 2));
    m1 = fmaxf(m1, __shfl_xor_sync(0xffffffffu, m1, 1));
    m1 = fmaxf(m1, __shfl_xor_sync(0xffffffffu, m1, 2));
    float s0 = 0.f, s1 = 0.f;
#pragma unroll
    for (int nt = 0; nt < 8; nt++) {
        float e0 = __expf(cqk[nt][0] - m0), e1 = __expf(cqk[nt][1] - m0);
        float e2 = __expf(cqk[nt][2] - m1), e3 = __expf(cqk[nt][3] - m1);
        cqk[nt][0] = e0; cqk[nt][1] = e1; cqk[nt][2] = e2; cqk[nt][3] = e3;
        s0 += e0 + e1; s1 += e2 + e3;
    }
    s0 += __shfl_xor_sync(0xffffffffu, s0, 1);
    s0 += __shfl_xor_sync(0xffffffffu, s0, 2);
    s1 += __shfl_xor_sync(0xffffffffu, s1, 1);
    s1 += __shfl_xor_sync(0xffffffffu, s1, 2);
    if (tig == 0) {
        stats[(wn * 64 + arow) * 2]         = m0;
        stats[(wn * 64 + arow) * 2 + 1]     = s0;
        stats[(wn * 64 + arow + 8) * 2]     = m1;
        stats[(wn * 64 + arow + 8) * 2 + 1] = s1;
    }
    BARP(1 + wm);
    float om0 = stats[((wn ^ 1) * 64 + arow) * 2];
    float os0 = stats[((wn ^ 1) * 64 + arow) * 2 + 1];
    float om1 = stats[((wn ^ 1) * 64 + arow + 8) * 2];
    float os1 = stats[((wn ^ 1) * 64 + arow + 8) * 2 + 1];
    float M0 = fmaxf(m0, om0), M1 = fmaxf(m1, om1);
    float S0 = s0 * __expf(m0 - M0) + os0 * __expf(om0 - M0);
    float S1 = s1 * __expf(m1 - M1) + os1 * __expf(om1 - M1);
    float sc0 = __expf(m0 - M0) / S0;
    float sc1 = __expf(m1 - M1) / S1;
    if (wn == 0 && tig == 0) {
        g_lse[((size_t)(b * HH + h)) * SS + tq0] = M0 + __logf(S0);
        g_lse[((size_t)(b * HH + h)) * SS + tq1] = M1 + __logf(S1);
    }

    // ---- P @ V over this warp's 64-key half; B via ldmatrix.trans from row-major Vsm
    float oacc[8][4];
#pragma unroll
    for (int ft = 0; ft < 8; ft++)
#pragma unroll
        for (int r = 0; r < 4; r++) oacc[ft][r] = 0.f;

#pragma unroll
    for (int s = 0; s < 4; s++) {
        unsigned a0 = h2_u32(__floats2half2_rn(cqk[2 * s][0] * sc0, cqk[2 * s][1] * sc0));
        unsigned a1 = h2_u32(__floats2half2_rn(cqk[2 * s][2] * sc1, cqk[2 * s][3] * sc1));
        unsigned a2 = h2_u32(__floats2half2_rn(cqk[2 * s + 1][0] * sc0, cqk[2 * s + 1][1] * sc0));
        unsigned a3 = h2_u32(__floats2half2_rn(cqk[2 * s + 1][2] * sc1, cqk[2 * s + 1][3] * sc1));
#pragma unroll
        for (int t = 0; t < 4; t++) {
            unsigned r0, r1, r2, r3;
            ldsm4t(r0, r1, r2, r3, vfragb + s * 16 * 144 + t * 32);
            mma_f16(oacc[2 * t],     a0, a1, a2, a3, r0, r1);
            mma_f16(oacc[2 * t + 1], a0, a1, a2, a3, r2, r3);
        }
    }

    // ---- sum wn partials via fp16 Dxh (pair barrier), store fp16 outputs by token position
    if (wn == 1) {
#pragma unroll
        for (int ft = 0; ft < 8; ft++) {
            *(__half2*)&Dxh[arow * 72 + ft * 8 + 2 * tig]       = __floats2half2_rn(oacc[ft][0], oacc[ft][1]);
            *(__half2*)&Dxh[(arow + 8) * 72 + ft * 8 + 2 * tig] = __floats2half2_rn(oacc[ft][2], oacc[ft][3]);
        }
    }
    BARP(1 + wm);
    if (wn == 0) {
        __half2* o0 = g_o + (((size_t)(b * HH + h)) * SS + tq0) * 32;
        __half2* o1 = g_o + (((size_t)(b * HH + h)) * SS + tq1) * 32;
#pragma unroll
        for (int ft = 0; ft < 8; ft++) {
            float2 d0 = __half22float2(*(__half2*)&Dxh[arow * 72 + ft * 8 + 2 * tig]);
            float2 d1 = __half22float2(*(__half2*)&Dxh[(arow + 8) * 72 + ft * 8 + 2 * tig]);
            o0[ft * 4 + tig] = __floats2half2_rn(oacc[ft][0] + d0.x, oacc[ft][1] + d0.y);
            o1[ft * 4 + tig] = __floats2half2_rn(oacc[ft][2] + d1.x, oacc[ft][3] + d1.y);
        }
    }
}

// ==================== Kernel 4: combine hash rounds ====================
__global__ __launch_bounds__(256) void combine_kernel(float* __restrict__ out) {
    const int gw = (blockIdx.x * 256 + threadIdx.x) >> 5;
    const int l  = threadIdx.x & 31;
    const int b  = gw >> 12, t = gw & (SS - 1);

    float lg[HH];
#pragma unroll
    for (int hh = 0; hh < HH; hh++) lg[hh] = g_lse[((size_t)(b * HH + hh)) * SS + t];
    float m = lg[0];
#pragma unroll
    for (int hh = 1; hh < HH; hh++) m = fmaxf(m, lg[hh]);
    float wv[HH];
    float wsum = 0.f;
#pragma unroll
    for (int hh = 0; hh < HH; hh++) { wv[hh] = __expf(lg[hh] - m); wsum += wv[hh]; }
    float inv = 1.0f / wsum;

    float2 accv = make_float2(0.f, 0.f);
#pragma unroll
    for (int hh = 0; hh < HH; hh++) {
        float2 ov = __half22float2(g_o[((((size_t)(b * HH + hh)) * SS + t) * 32) + l]);
        float wgt = wv[hh] * inv;
        accv.x += wgt * ov.x;
        accv.y += wgt * ov.y;
    }
    ((float2*)(out + ((size_t)b * SS + t) * DD))[l] = accv;
}

// ==================== launch ====================
extern "C" void kernel_launch(void* const* d_in, const int* in_sizes, int n_in,
                              void* d_out, int out_size) {
    const float* qk  = (const float*)d_in[0];
    const float* v   = (const float*)d_in[1];
    const float* rot = (const float*)d_in[2];
    float* out = (float*)d_out;

    (void)in_sizes; (void)n_in; (void)out_size;

    const int hash_smem = 87040;   // 64*68*4 + 256*68*4
    const int attn_smem = 57088;   // tqi/tki/stats + Qsm + Ksm + Vsm + Dxh
    cudaFuncSetAttribute(hash_kernel, cudaFuncAttributeMaxDynamicSharedMemorySize, hash_smem);
    cudaFuncSetAttribute(attn_kernel, cudaFuncAttributeMaxDynamicSharedMemorySize, attn_smem);

    hash_kernel<<<BB * (SS / 64), 256, hash_smem>>>(qk, v, rot);
    sort_kernel<<<BB * HH, 512>>>();
    attn_kernel<<<BB * CHK, 256, attn_smem>>>();
    combine_kernel<<<(BB * SS) / 8, 256>>>(out);
}

// round 12
// speedup vs baseline: 2.2814x; 1.0092x over previous
#include <cuda_runtime.h>
#include <cuda_fp16.h>
#include <math.h>

// Problem constants (fixed shapes from reference)
#define BB 16
#define SS 4096
#define DD 64
#define HH 8
#define NBK 64          // buckets per hash round
#define CHK 512         // chunks per batch (HH * NBK)
#define BSZ 64          // bucket/chunk size
#define KVN 128         // keys per chunk (current + look-back)

// -------------------- device scratch (no allocation allowed) --------------------
__device__ int     g_buckets[BB * HH * SS];               // 2 MB
__device__ int     g_st[BB * HH * SS];                    // 2 MB  sorted original positions
__device__ float   g_lse[BB * HH * SS];                   // 2 MB  per-round logits (unsorted layout)
__device__ __half2 g_o[(size_t)BB * HH * SS * 32];        // 67 MB per-round outputs (fp16, unsorted)
__device__ __half2 g_qh[(size_t)BB * SS * 32];            // 8 MB  fp16 q * D^-0.5
__device__ __half2 g_kh[(size_t)BB * SS * 32];            // 8 MB  fp16 normalized k
__device__ __half2 g_vh[(size_t)BB * SS * 32];            // 8 MB  fp16 v

// -------------------- helpers --------------------
__device__ __forceinline__ unsigned h2_u32(__half2 h) {
    union { __half2 h; unsigned u; } cvt;
    cvt.h = h;
    return cvt.u;
}

__device__ __forceinline__ void mma_f16(float* c,
                                        unsigned a0, unsigned a1, unsigned a2, unsigned a3,
                                        unsigned b0, unsigned b1) {
    asm volatile("mma.sync.aligned.m16n8k16.row.col.f32.f16.f16.f32 "
                 "{%0,%1,%2,%3},{%4,%5,%6,%7},{%8,%9},{%0,%1,%2,%3};"
                 : "+f"(c[0]), "+f"(c[1]), "+f"(c[2]), "+f"(c[3])
                 : "r"(a0), "r"(a1), "r"(a2), "r"(a3), "r"(b0), "r"(b1));
}

__device__ __forceinline__ void ldsm4(unsigned& r0, unsigned& r1, unsigned& r2, unsigned& r3,
                                      unsigned addr) {
    asm volatile("ldmatrix.sync.aligned.m8n8.x4.shared.b16 {%0,%1,%2,%3}, [%4];"
                 : "=r"(r0), "=r"(r1), "=r"(r2), "=r"(r3) : "r"(addr));
}

__device__ __forceinline__ void ldsm4t(unsigned& r0, unsigned& r1, unsigned& r2, unsigned& r3,
                                       unsigned addr) {
    asm volatile("ldmatrix.sync.aligned.m8n8.x4.trans.shared.b16 {%0,%1,%2,%3}, [%4];"
                 : "=r"(r0), "=r"(r1), "=r"(r2), "=r"(r3) : "r"(addr));
}

__device__ __forceinline__ void cp16(unsigned dst, const void* src) {
    asm volatile("cp.async.cg.shared.global [%0], [%1], 16;" :: "r"(dst), "l"(src) : "memory");
}

// packed f32x2 helpers (Blackwell)
__device__ __forceinline__ unsigned long long pack2(float x, float y) {
    unsigned long long r;
    asm("mov.b64 %0, {%1, %2};" : "=l"(r) : "f"(x), "f"(y));
    return r;
}
__device__ __forceinline__ void unpack2(float& x, float& y, unsigned long long p) {
    asm("mov.b64 {%0, %1}, %2;" : "=f"(x), "=f"(y) : "l"(p));
}
__device__ __forceinline__ void fma2(unsigned long long& d, unsigned long long a, unsigned long long b) {
    asm("fma.rn.f32x2 %0, %1, %2, %0;" : "+l"(d) : "l"(a), "l"(b));
}

// pair barrier: warps {wm, wm+4} (64 threads), ids 1..4
#define BARP(id) asm volatile("bar.sync %0, 64;" :: "r"(id) : "memory")

// ==================== Kernel 1: LSH hashing (fp32 f32x2) + fused fp16 prep ====================
// grid = BB * (SS/64) = 1024 CTAs, 256 threads.
__global__ __launch_bounds__(256, 2) void hash_kernel(const float* __restrict__ qk,
                                                      const float* __restrict__ v,
                                                      const float* __restrict__ rot) {
    extern __shared__ float sm[];
    float* qT  = sm;              // 64*68 floats
    float* big = sm + 64 * 68;    // max(64*260, 256*68) = 17408 floats

    const int blk  = blockIdx.x;
    const int b    = blk >> 6;
    const int t0   = (blk & 63) * 64;
    const int tid  = threadIdx.x;
    const int w    = tid >> 5, l = tid & 31;

    {
        const float4* rg = (const float4*)rot;
        for (int i4 = tid; i4 < 64 * 64; i4 += 256) {
            int f = i4 >> 6, o4 = i4 & 63;
            *(float4*)&big[f * 260 + o4 * 4] = rg[i4];
        }
    }
    // q tile load (transposed into qT) + fused prep: qh, kh, vh
    for (int r = 0; r < 8; r++) {
        int i = w * 8 + r;
        size_t gi = (size_t)b * SS + t0 + i;
        float2 qv = ((const float2*)(qk + gi * DD))[l];
        qT[(2 * l) * 68 + i]     = qv.x;
        qT[(2 * l + 1) * 68 + i] = qv.y;
        float ssq = qv.x * qv.x + qv.y * qv.y;
#pragma unroll
        for (int o = 16; o; o >>= 1) ssq += __shfl_xor_sync(0xffffffffu, ssq, o);
        float inv = 1.0f / fmaxf(sqrtf(ssq), 1e-12f);
        g_kh[gi * 32 + l] = __floats2half2_rn(qv.x * inv, qv.y * inv);
        g_qh[gi * 32 + l] = __floats2half2_rn(qv.x * 0.125f, qv.y * 0.125f);
        float2 vv = ((const float2*)(v + gi * DD))[l];
        g_vh[gi * 32 + l] = __floats2half2_rn(vv.x, vv.y);
    }
    __syncthreads();

    const int rt = tid >> 4, ct = tid & 15;
    unsigned long long acc2[4][8];
#pragma unroll
    for (int r = 0; r < 4; r++)
#pragma unroll
        for (int p = 0; p < 8; p++) acc2[r][p] = pack2(0.f, 0.f);

    const float4* qT4 = (const float4*)qT;   // stride 17
    const float4* rt4 = (const float4*)big;  // stride 65
#pragma unroll 4
    for (int f = 0; f < 64; f++) {
        float4 q = qT4[f * 17 + rt];
        unsigned long long qq[4];
        qq[0] = pack2(q.x, q.x); qq[1] = pack2(q.y, q.y);
        qq[2] = pack2(q.z, q.z); qq[3] = pack2(q.w, q.w);
#pragma unroll
        for (int g = 0; g < 4; g++) {
            float4 rv = rt4[f * 65 + g * 16 + ct];
            unsigned long long r0 = pack2(rv.x, rv.y);
            unsigned long long r1 = pack2(rv.z, rv.w);
#pragma unroll
            for (int r = 0; r < 4; r++) {
                fma2(acc2[r][g * 2],     qq[r], r0);
                fma2(acc2[r][g * 2 + 1], qq[r], r1);
            }
        }
    }
    float acc[4][16];
#pragma unroll
    for (int r = 0; r < 4; r++)
#pragma unroll
        for (int p = 0; p < 8; p++)
            unpack2(acc[r][p * 2], acc[r][p * 2 + 1], acc2[r][p]);
    __syncthreads();   // rot dead, reuse region as dsH[o][t] stride 68

    float* dsH = big;
#pragma unroll
    for (int g = 0; g < 4; g++)
#pragma unroll
        for (int c = 0; c < 4; c++) {
            int o = g * 64 + ct * 4 + c;
            *(float4*)&dsH[o * 68 + rt * 4] =
                make_float4(acc[0][g * 4 + c], acc[1][g * 4 + c], acc[2][g * 4 + c], acc[3][g * 4 + c]);
        }
    __syncthreads();

    for (int p = tid; p < 512; p += 256) {
        int t = p & 63, hh = p >> 6;
        const float* dv = &dsH[(hh * 32) * 68 + t];
        float best = dv[0];
        int bi = 0;
#pragma unroll
        for (int j = 1; j < 32; j++) { float vv = dv[j * 68];  if (vv > best) { best = vv; bi = j; } }
#pragma unroll
        for (int j = 0; j < 32; j++) { float vv = -dv[j * 68]; if (vv > best) { best = vv; bi = 32 + j; } }
        g_buckets[((size_t)(b * HH + hh)) * SS + t0 + t] = bi;
    }
}

// ==================== Kernel 2: stable counting sort per (b,h) ====================
__global__ __launch_bounds__(512) void sort_kernel() {
    __shared__ int hist[16][64];
    __shared__ int run[16][64];
    __shared__ int totals[64];
    __shared__ int bstart[64];

    const int bh  = blockIdx.x;
    const int* bk = g_buckets + (size_t)bh * SS;
    int* dst      = g_st + (size_t)bh * SS;
    const int tid = threadIdx.x, w = tid >> 5, l = tid & 31;

    for (int i = tid; i < 1024; i += 512) ((int*)hist)[i] = 0;
    __syncthreads();

    for (int r = 0; r < 8; r++) {
        int t = w * 256 + r * 32 + l;
        int vv = bk[t];
        unsigned mask = __match_any_sync(0xffffffffu, vv);
        if (l == (int)(__ffs(mask) - 1)) hist[w][vv] += __popc(mask);
        __syncwarp();
    }
    __syncthreads();

    if (tid < 64) {
        int s = 0;
        for (int ww = 0; ww < 16; ww++) { int tmp = hist[ww][tid]; hist[ww][tid] = s; s += tmp; }
        totals[tid] = s;
    }
    __syncthreads();
    if (tid == 0) {
        int s = 0;
        for (int vv = 0; vv < 64; vv++) { bstart[vv] = s; s += totals[vv]; }
    }
    __syncthreads();
    for (int i = tid; i < 1024; i += 512) {
        int ww = i >> 6, vv = i & 63;
        run[ww][vv] = bstart[vv] + hist[ww][vv];
    }
    __syncthreads();

    for (int r = 0; r < 8; r++) {
        int t = w * 256 + r * 32 + l;
        int vv = bk[t];
        unsigned mask = __match_any_sync(0xffffffffu, vv);
        int rank = __popc(mask & ((1u << l) - 1u));
        int base = run[w][vv];
        __syncwarp();
        if (l == (int)(__ffs(mask) - 1)) run[w][vv] = base + __popc(mask);
        __syncwarp();
        dst[base + rank] = t;
    }
}

// ==================== Kernel 3: chunked attention (cp.async + ldmatrix + fp16 mma) ====================
// grid = BB*CHK = 8192 CTAs, 256 threads (8 warps), 57088B smem, 4 CTAs/SM (64 regs).
__global__ __launch_bounds__(256, 4) void attn_kernel() {
    extern __shared__ char smc[];
    int*    tqi   = (int*)smc;                  // 64 ints
    int*    tki   = (int*)(smc + 256);          // 128 ints
    float*  stats = (float*)(smc + 768);        // 256 floats: [wn*64+row]*2 -> {m,s}
    __half* Qsm   = (__half*)(smc + 1792);      // 64  x 144B
    __half* Ksm   = (__half*)(smc + 11008);     // 128 x 144B
    __half* Vsm   = (__half*)(smc + 29440);     // 128 x 144B (row-major)
    __half* Dxh   = (__half*)(smc + 47872);     // 64 x 144B (72-half rows), fp16 PV partials

    const int blk = blockIdx.x;
    const int b = blk >> 9, c = blk & 511;
    const int h  = c >> 6;
    const int cp = (c + 511) & 511;
    const int hp = cp >> 6;
    const int tid = threadIdx.x, w = tid >> 5, l = tid & 31;
    const int gID = l >> 2, tig = l & 3;
    const int wm = w & 3, wn = w >> 2;
    const int arow = wm * 16 + gID;

    if (tid < 64) {
        int t = g_st[((size_t)(b * HH + h)) * SS + (c & 63) * 64 + tid];
        tqi[tid] = t;
        tki[tid] = t;
    } else if (tid < 128) {
        int i = tid - 64;
        tki[64 + i] = g_st[((size_t)(b * HH + hp)) * SS + (cp & 63) * 64 + i];
    }
    __syncthreads();

    // ---- gather via cp.async: 16B chunks, 8 per 128B row
    {
        unsigned q_u32 = (unsigned)__cvta_generic_to_shared(Qsm);
        unsigned k_u32 = (unsigned)__cvta_generic_to_shared(Ksm);
        unsigned v_u32 = (unsigned)__cvta_generic_to_shared(Vsm);
        const char* qh = (const char*)g_qh + (size_t)b * SS * 128;
        const char* kh = (const char*)g_kh + (size_t)b * SS * 128;
        const char* vh = (const char*)g_vh + (size_t)b * SS * 128;
#pragma unroll
        for (int it = 0; it < 2; it++) {           // 64 q rows
            int slot = tid + it * 256;
            int row = slot >> 3, ch = slot & 7;
            cp16(q_u32 + row * 144 + ch * 16, qh + (size_t)tqi[row] * 128 + ch * 16);
        }
#pragma unroll
        for (int it = 0; it < 4; it++) {           // 128 k rows
            int slot = tid + it * 256;
            int row = slot >> 3, ch = slot & 7;
            cp16(k_u32 + row * 144 + ch * 16, kh + (size_t)tki[row] * 128 + ch * 16);
        }
#pragma unroll
        for (int it = 0; it < 4; it++) {           // 128 v rows
            int slot = tid + it * 256;
            int row = slot >> 3, ch = slot & 7;
            cp16(v_u32 + row * 144 + ch * 16, vh + (size_t)tki[row] * 128 + ch * 16);
        }
        asm volatile("cp.async.commit_group;" ::: "memory");
        asm volatile("cp.async.wait_group 0;" ::: "memory");
    }
    __syncthreads();

    // ---- ldmatrix lane addressing
    const int lrow = (l & 7) + ((l >> 3) & 1) * 8;
    const int lcsh = ((l >> 4) & 1) * 16;          // bytes
    const unsigned qfrag = (unsigned)__cvta_generic_to_shared(Qsm) + (wm * 16 + lrow) * 144 + lcsh;
    const unsigned kfragb = (unsigned)__cvta_generic_to_shared(Ksm) + (wn * 64 + lrow) * 144 + lcsh;
    const unsigned vfragb = (unsigned)__cvta_generic_to_shared(Vsm) + (wn * 64 + lrow) * 144 + lcsh;

    // ---- QK^T via fp16 mma (K=64: 4 k16 steps; 8 n-tiles as 4 pairs)
    float cqk[8][4];
#pragma unroll
    for (int nt = 0; nt < 8; nt++)
#pragma unroll
        for (int r = 0; r < 4; r++) cqk[nt][r] = 0.f;

#pragma unroll
    for (int s = 0; s < 4; s++) {
        unsigned a0, a1, a2, a3;
        ldsm4(a0, a1, a2, a3, qfrag + s * 32);
#pragma unroll
        for (int p = 0; p < 4; p++) {
            unsigned b00, b01, b10, b11;
            ldsm4(b00, b01, b10, b11, kfragb + p * 16 * 144 + s * 32);
            mma_f16(cqk[2 * p],     a0, a1, a2, a3, b00, b10);
            mma_f16(cqk[2 * p + 1], a0, a1, a2, a3, b01, b11);
        }
    }

    // ---- self-mask
    const int tq0 = tqi[arow], tq1 = tqi[arow + 8];
#pragma unroll
    for (int nt = 0; nt < 8; nt++) {
        int2 kk = *(int2*)&tki[wn * 64 + nt * 8 + 2 * tig];
        if (kk.x == tq0) cqk[nt][0] = -5e4f;
        if (kk.y == tq0) cqk[nt][1] = -5e4f;
        if (kk.x == tq1) cqk[nt][2] = -5e4f;
        if (kk.y == tq1) cqk[nt][3] = -5e4f;
    }

    // ---- register softmax: per-row partial (m, s), merge across wn via pair barrier
    float m0 = -3.4e38f, m1 = -3.4e38f;
#pragma unroll
    for (int nt = 0; nt < 8; nt++) {
        m0 = fmaxf(m0, fmaxf(cqk[nt][0], cqk[nt][1]));
        m1 = fmaxf(m1, fmaxf(cqk[nt][2], cqk[nt][3]));
    }
    m0 = fmaxf(m0, __shfl_xor_sync(0xffffffffu, m0, 1));
    m0 = fmaxf(m0, __shfl_xor_sync(0xffffffffu, m0, 2));
    m1 = fmaxf(m1, __shfl_xor_sync(0xffffffffu, m1, 1));
    m1 = fmaxf(m1, __shfl_xor_sync(0xffffffffu, m1, 2));
    float s0 = 0.f, s1 = 0.f;
#pragma unroll
    for (int nt = 0; nt < 8; nt++) {
        float e0 = __expf(cqk[nt][0] - m0), e1 = __expf(cqk[nt][1] - m0);
        float e2 = __expf(cqk[nt][2] - m1), e3 = __expf(cqk[nt][3] - m1);
        cqk[nt][0] = e0; cqk[nt][1] = e1; cqk[nt][2] = e2; cqk[nt][3] = e3;
        s0 += e0 + e1; s1 += e2 + e3;
    }
    s0 += __shfl_xor_sync(0xffffffffu, s0, 1);
    s0 += __shfl_xor_sync(0xffffffffu, s0, 2);
    s1 += __shfl_xor_sync(0xffffffffu, s1, 1);
    s1 += __shfl_xor_sync(0xffffffffu, s1, 2);
    if (tig == 0) {
        stats[(wn * 64 + arow) * 2]         = m0;
        stats[(wn * 64 + arow) * 2 + 1]     = s0;
        stats[(wn * 64 + arow + 8) * 2]     = m1;
        stats[(wn * 64 + arow + 8) * 2 + 1] = s1;
    }
    BARP(1 + wm);
    float om0 = stats[((wn ^ 1) * 64 + arow) * 2];
    float os0 = stats[((wn ^ 1) * 64 + arow) * 2 + 1];
    float om1 = stats[((wn ^ 1) * 64 + arow + 8) * 2];
    float os1 = stats[((wn ^ 1) * 64 + arow + 8) * 2 + 1];
    float M0 = fmaxf(m0, om0), M1 = fmaxf(m1, om1);
    float S0 = s0 * __expf(m0 - M0) + os0 * __expf(om0 - M0);
    float S1 = s1 * __expf(m1 - M1) + os1 * __expf(om1 - M1);
    float sc0 = __expf(m0 - M0) / S0;
    float sc1 = __expf(m1 - M1) / S1;
    if (wn == 0 && tig == 0) {
        g_lse[((size_t)(b * HH + h)) * SS + tq0] = M0 + __logf(S0);
        g_lse[((size_t)(b * HH + h)) * SS + tq1] = M1 + __logf(S1);
    }

    // ---- convert ALL PV A-fragments up front (cqk dies here -> peak regs drop)
    unsigned af[4][4];
#pragma unroll
    for (int s = 0; s < 4; s++) {
        af[s][0] = h2_u32(__floats2half2_rn(cqk[2 * s][0] * sc0, cqk[2 * s][1] * sc0));
        af[s][1] = h2_u32(__floats2half2_rn(cqk[2 * s][2] * sc1, cqk[2 * s][3] * sc1));
        af[s][2] = h2_u32(__floats2half2_rn(cqk[2 * s + 1][0] * sc0, cqk[2 * s + 1][1] * sc0));
        af[s][3] = h2_u32(__floats2half2_rn(cqk[2 * s + 1][2] * sc1, cqk[2 * s + 1][3] * sc1));
    }

    // ---- P @ V over this warp's 64-key half; B via ldmatrix.trans from row-major Vsm
    float oacc[8][4];
#pragma unroll
    for (int ft = 0; ft < 8; ft++)
#pragma unroll
        for (int r = 0; r < 4; r++) oacc[ft][r] = 0.f;

#pragma unroll
    for (int s = 0; s < 4; s++) {
#pragma unroll
        for (int t = 0; t < 4; t++) {
            unsigned r0, r1, r2, r3;
            ldsm4t(r0, r1, r2, r3, vfragb + s * 16 * 144 + t * 32);
            mma_f16(oacc[2 * t],     af[s][0], af[s][1], af[s][2], af[s][3], r0, r1);
            mma_f16(oacc[2 * t + 1], af[s][0], af[s][1], af[s][2], af[s][3], r2, r3);
        }
    }

    // ---- sum wn partials via fp16 Dxh (pair barrier), store fp16 outputs by token position
    if (wn == 1) {
#pragma unroll
        for (int ft = 0; ft < 8; ft++) {
            *(__half2*)&Dxh[arow * 72 + ft * 8 + 2 * tig]       = __floats2half2_rn(oacc[ft][0], oacc[ft][1]);
            *(__half2*)&Dxh[(arow + 8) * 72 + ft * 8 + 2 * tig] = __floats2half2_rn(oacc[ft][2], oacc[ft][3]);
        }
    }
    BARP(1 + wm);
    if (wn == 0) {
        __half2* o0 = g_o + (((size_t)(b * HH + h)) * SS + tq0) * 32;
        __half2* o1 = g_o + (((size_t)(b * HH + h)) * SS + tq1) * 32;
#pragma unroll
        for (int ft = 0; ft < 8; ft++) {
            float2 d0 = __half22float2(*(__half2*)&Dxh[arow * 72 + ft * 8 + 2 * tig]);
            float2 d1 = __half22float2(*(__half2*)&Dxh[(arow + 8) * 72 + ft * 8 + 2 * tig]);
            o0[ft * 4 + tig] = __floats2half2_rn(oacc[ft][0] + d0.x, oacc[ft][1] + d0.y);
            o1[ft * 4 + tig] = __floats2half2_rn(oacc[ft][2] + d1.x, oacc[ft][3] + d1.y);
        }
    }
}

// ==================== Kernel 4: combine hash rounds ====================
__global__ __launch_bounds__(256) void combine_kernel(float* __restrict__ out) {
    const int gw = (blockIdx.x * 256 + threadIdx.x) >> 5;
    const int l  = threadIdx.x & 31;
    const int b  = gw >> 12, t = gw & (SS - 1);

    float lg[HH];
#pragma unroll
    for (int hh = 0; hh < HH; hh++) lg[hh] = g_lse[((size_t)(b * HH + hh)) * SS + t];
    float m = lg[0];
#pragma unroll
    for (int hh = 1; hh < HH; hh++) m = fmaxf(m, lg[hh]);
    float wv[HH];
    float wsum = 0.f;
#pragma unroll
    for (int hh = 0; hh < HH; hh++) { wv[hh] = __expf(lg[hh] - m); wsum += wv[hh]; }
    float inv = 1.0f / wsum;

    float2 accv = make_float2(0.f, 0.f);
#pragma unroll
    for (int hh = 0; hh < HH; hh++) {
        float2 ov = __half22float2(g_o[((((size_t)(b * HH + hh)) * SS + t) * 32) + l]);
        float wgt = wv[hh] * inv;
        accv.x += wgt * ov.x;
        accv.y += wgt * ov.y;
    }
    ((float2*)(out + ((size_t)b * SS + t) * DD))[l] = accv;
}

// ==================== launch ====================
extern "C" void kernel_launch(void* const* d_in, const int* in_sizes, int n_in,
                              void* d_out, int out_size) {
    const float* qk  = (const float*)d_in[0];
    const float* v   = (const float*)d_in[1];
    const float* rot = (const float*)d_in[2];
    float* out = (float*)d_out;

    (void)in_sizes; (void)n_in; (void)out_size;

    const int hash_smem = 87040;   // 64*68*4 + 256*68*4
    const int attn_smem = 57088;   // tqi/tki/stats + Qsm + Ksm + Vsm + Dxh
    cudaFuncSetAttribute(hash_kernel, cudaFuncAttributeMaxDynamicSharedMemorySize, hash_smem);
    cudaFuncSetAttribute(attn_kernel, cudaFuncAttributeMaxDynamicSharedMemorySize, attn_smem);

    hash_kernel<<<BB * (SS / 64), 256, hash_smem>>>(qk, v, rot);
    sort_kernel<<<BB * HH, 512>>>();
    attn_kernel<<<BB * CHK, 256, attn_smem>>>();
    combine_kernel<<<(BB * SS) / 8, 256>>>(out);
}